// round 14
// baseline (speedup 1.0000x reference)
#include <cuda_runtime.h>
#include <cuda_fp16.h>
#include <cstdint>

#define BB    16
#define LSEQ  1024
#define DIN   512
#define NKC   512
#define HH    8
#define DHH   64
#define LC    1022
#define LCP   1024
#define NLB   1024
#define ADIM  256

// ---------- scratch (zero-init; pads never written) ----------
__device__ float g_o1[BB * NLB * NKC];
__device__ float g_o2[BB * NLB * NKC];
__device__ __align__(16) __half g_q1h[BB * NKC * LCP];
__device__ __align__(16) __half g_k1h[BB * NKC * LCP];
__device__ __align__(16) __half g_v1h[BB * NKC * LCP];
__device__ __align__(16) __half g_c1h[BB * LC * NKC];
__device__ __align__(16) __half g_t1h[BB * LC * ADIM];
__device__ __align__(16) __half g_sch[BB * NLB * LCP];
__device__ __align__(16) __half g_b2sh[BB * NLB * LCP];
__device__ __align__(16) __half g_ebh[BB * LSEQ * DIN];
__device__ __align__(16) __half g_wh[3][3 * NKC * DIN];
__device__ __align__(16) __half g_labh[NLB * NKC];
__device__ __align__(16) __half g_w1h[ADIM * NKC];
__device__ __align__(16) __half g_w2h[NLB * ADIM];

// ---------- smem: 3-buffer ring, per buffer A(10240) B(10240) ----------
#define BHOFF 10240
#define BUFB  20480
#define SMEMB (3 * BUFB)

__device__ __forceinline__ uint32_t s2u(const void* p) {
    uint32_t a;
    asm("{ .reg .u64 t; cvta.to.shared.u64 t, %1; cvt.u32.u64 %0, t; }" : "=r"(a) : "l"(p));
    return a;
}
__device__ __forceinline__ void ldm4(uint32_t* r, uint32_t addr) {
    asm volatile("ldmatrix.sync.aligned.m8n8.x4.shared.b16 {%0,%1,%2,%3}, [%4];"
                 : "=r"(r[0]), "=r"(r[1]), "=r"(r[2]), "=r"(r[3]) : "r"(addr));
}
__device__ __forceinline__ void mmah(float* c, const uint32_t* a, const uint32_t* b) {
    asm volatile("mma.sync.aligned.m16n8k16.row.col.f32.f16.f16.f32 "
                 "{%0,%1,%2,%3}, {%4,%5,%6,%7}, {%8,%9}, {%0,%1,%2,%3};"
                 : "+f"(c[0]), "+f"(c[1]), "+f"(c[2]), "+f"(c[3])
                 : "r"(a[0]), "r"(a[1]), "r"(a[2]), "r"(a[3]), "r"(b[0]), "r"(b[1]));
}
// fp16-accumulate MMA (hypothesized 2x rate)
__device__ __forceinline__ void mmah16(uint32_t* c, const uint32_t* a, const uint32_t* b) {
    asm volatile("mma.sync.aligned.m16n8k16.row.col.f16.f16.f16.f16 "
                 "{%0,%1}, {%2,%3,%4,%5}, {%6,%7}, {%0,%1};"
                 : "+r"(c[0]), "+r"(c[1])
                 : "r"(a[0]), "r"(a[1]), "r"(a[2]), "r"(a[3]), "r"(b[0]), "r"(b[1]));
}
__device__ __forceinline__ void cpa16z(uint32_t d, const void* s, int sz) {
    asm volatile("cp.async.cg.shared.global [%0], [%1], 16, %2;" :: "r"(d), "l"(s), "r"(sz));
}
__device__ __forceinline__ void waitg(bool last) {
    if (last) asm volatile("cp.async.wait_group 0;");
    else      asm volatile("cp.async.wait_group 1;");
}

__device__ __forceinline__ uint32_t h2u(__half2 v) { return *reinterpret_cast<uint32_t*>(&v); }
__device__ __forceinline__ uint32_t pkh(float x, float y) {
    __half2 h = __floats2half2_rn(x, y);
    return h2u(h);
}
__device__ __forceinline__ uint2 cvt4hi(float4 v) {
    return make_uint2(h2u(__floats2half2_rn(v.x, v.y)), h2u(__floats2half2_rn(v.z, v.w)));
}
__device__ __forceinline__ void sth2(__half* p, float x, float y) {
    *(__half2*)p = __floats2half2_rn(x, y);
}
// promote 16 f16 fragments into fp32 accumulators and clear
__device__ __forceinline__ void promote(float (&acc)[2][8][4], uint32_t (&hacc)[2][8][2]) {
#pragma unroll
    for (int mi = 0; mi < 2; ++mi)
#pragma unroll
        for (int ni = 0; ni < 8; ++ni) {
            float2 p0 = __half22float2(*(__half2*)&hacc[mi][ni][0]);
            float2 p1 = __half22float2(*(__half2*)&hacc[mi][ni][1]);
            acc[mi][ni][0] += p0.x; acc[mi][ni][1] += p0.y;
            acc[mi][ni][2] += p1.x; acc[mi][ni][3] += p1.y;
            hacc[mi][ni][0] = 0u;   hacc[mi][ni][1] = 0u;
        }
}

// ---------- input conversion kernels ----------
__global__ void split_emb(const float* __restrict__ e) {
    size_t i = ((size_t)blockIdx.x * 256 + threadIdx.x) * 4;
    *(uint2*)(g_ebh + i) = cvt4hi(*(const float4*)(e + i));
}
__global__ void repack_w_all(const float* __restrict__ wq, const float* __restrict__ wk,
                             const float* __restrict__ wv) {
    int idx = blockIdx.x * 256 + threadIdx.x;
    const float* ws[3] = {wq, wk, wv};
#pragma unroll
    for (int wsel = 0; wsel < 3; ++wsel)
#pragma unroll
        for (int t = 0; t < 3; ++t)
            g_wh[wsel][t * NKC * DIN + idx] = __float2half_rn(ws[wsel][idx * 3 + t]);
}
__global__ void cvt_misc(const float* __restrict__ lab, const float* __restrict__ w1,
                         const float* __restrict__ w2) {
    int i = blockIdx.x * 256 + threadIdx.x;
    if (i < 131072) *(uint2*)(g_labh + i * 4) = cvt4hi(((const float4*)lab)[i]);
    if (i < 32768)  *(uint2*)(g_w1h + i * 4) = cvt4hi(((const float4*)w1)[i]);
    if (i < 65536)  *(uint2*)(g_w2h + i * 4) = cvt4hi(((const float4*)w2)[i]);
}

// ================= conv: 128x128 tile, ring-3, f16-acc inner =================
template <int W>
__global__ void __launch_bounds__(256) convtc(const float* __restrict__ bias) {
    extern __shared__ __align__(128) char smem[];
    int tid = threadIdx.x, lane = tid & 31, wid = tid >> 5;
    int bx = blockIdx.x, by = blockIdx.y, z = blockIdx.z;
    int warpM = wid & 3, warpN = wid >> 2;

    auto issue = [&](int c) {
        char* buf = smem + (c % 3) * BUFB;
        int t3 = c >> 4, i0 = (c & 15) * 32;
        const __half* Ah = g_wh[W] + (size_t)(t3 * NKC + bx * 128) * DIN + i0;
        uint32_t sA = s2u(buf), sB = s2u(buf + BHOFF);
#pragma unroll
        for (int q = 0; q < 2; ++q) {
            int ca = tid + q * 256, r = ca >> 2, ch = ca & 3;
            cpa16z(sA + r * 80 + ch * 16, Ah + (size_t)r * DIN + ch * 8, 16);
            int lrow = by * 128 + t3 + r;
            int sz = (lrow < LSEQ) ? 16 : 0;
            int lcl = (lrow < LSEQ) ? lrow : (LSEQ - 1);
            cpa16z(sB + r * 80 + ch * 16,
                   g_ebh + ((size_t)z * LSEQ + lcl) * DIN + i0 + ch * 8, sz);
        }
        asm volatile("cp.async.commit_group;");
    };

    float acc[2][8][4];
    uint32_t hacc[2][8][2];
#pragma unroll
    for (int a = 0; a < 2; ++a)
#pragma unroll
        for (int b2 = 0; b2 < 8; ++b2) {
#pragma unroll
            for (int e = 0; e < 4; ++e) acc[a][b2][e] = 0.f;
            hacc[a][b2][0] = 0u; hacc[a][b2][1] = 0u;
        }

    issue(0);
    issue(1);
    for (int c = 0; c < 48; ++c) {
        waitg(c + 1 >= 48);
        __syncthreads();
        if (c + 2 < 48) issue(c + 2);
        char* buf = smem + (c % 3) * BUFB;
        uint32_t sA = s2u(buf), sB = s2u(buf + BHOFF);
#pragma unroll
        for (int kb = 0; kb < 2; ++kb) {
            uint32_t ah[2][4];
#pragma unroll
            for (int mi = 0; mi < 2; ++mi)
                ldm4(ah[mi], sA + ((warpM * 32 + mi * 16 + (lane & 15)) * 40 +
                                   kb * 16 + (lane >> 4) * 8) * 2);
            uint32_t bh[4][4];
#pragma unroll
            for (int g = 0; g < 4; ++g)
                ldm4(bh[g], sB + ((warpN * 64 + g * 16 + (lane & 7) + ((lane >> 4) & 1) * 8) * 40 +
                                  kb * 16 + ((lane >> 3) & 1) * 8) * 2);
#pragma unroll
            for (int mi = 0; mi < 2; ++mi)
#pragma unroll
                for (int ni = 0; ni < 8; ++ni)
                    mmah16(hacc[mi][ni], ah[mi], &bh[ni >> 1][(ni & 1) * 2]);
        }
        if ((c & 1) == 1) promote(acc, hacc);
    }

    __half* outp = (W == 0) ? g_q1h : (W == 1) ? g_k1h : g_v1h;
    int r0 = lane >> 2, c0 = (lane & 3) * 2;
    int vm = LC - by * 128; if (vm > 128) vm = 128;
#pragma unroll
    for (int mi = 0; mi < 2; ++mi)
#pragma unroll
        for (int rh = 0; rh < 2; ++rh) {
            int m = warpM * 32 + mi * 16 + r0 + rh * 8;
            float bv = bias[bx * 128 + m];
            __half* dst = outp + ((size_t)z * NKC + bx * 128 + m) * LCP + by * 128;
#pragma unroll
            for (int ni = 0; ni < 8; ++ni) {
                int col = warpN * 64 + ni * 8 + c0;
                if (col < vm) {
                    float v0 = acc[mi][ni][rh * 2 + 0] + bv;
                    float v1 = acc[mi][ni][rh * 2 + 1] + bv;
                    v0 = v0 > 0.f ? v0 : (__expf(v0) - 1.f);
                    v1 = v1 > 0.f ? v1 : (__expf(v1) - 1.f);
                    sth2(dst + col, v0, v1);
                }
            }
        }
}

// ================= flash attention (unchanged, proven) =================
#define FSM 36864
__global__ void __launch_bounds__(256) flash_attn() {
    extern __shared__ __align__(128) char smem[];
    constexpr int QH = 0, KH = 18432, VH = 27648;
    int tid = threadIdx.x, lane = tid & 31, w = tid >> 5;
    int l0 = blockIdx.x * 128, z = blockIdx.y, bb = z >> 3, hh = z & 7;
    const __half* qb = g_q1h + ((size_t)(bb * NKC + hh * DHH)) * LCP;
    const __half* kb = g_k1h + ((size_t)(bb * NKC + hh * DHH)) * LCP;
    const __half* vb = g_v1h + ((size_t)(bb * NKC + hh * DHH)) * LCP;

    {
        int d = tid >> 2, lc = (tid & 3) * 32;
        const __half* p = qb + (size_t)d * LCP + l0 + lc;
#pragma unroll
        for (int j = 0; j < 4; ++j) {
            uint4 v = *(const uint4*)(p + j * 8);
            const __half* hv = (const __half*)&v;
#pragma unroll
            for (int e = 0; e < 8; ++e)
                *(__half*)(smem + QH + ((lc + j * 8 + e) * 72 + d) * 2) = hv[e];
        }
    }

    float OA[8][4];
#pragma unroll
    for (int i = 0; i < 8; ++i)
#pragma unroll
        for (int e = 0; e < 4; ++e) OA[i][e] = 0.f;
    float mrow0 = -1e30f, mrow1 = -1e30f, lrow0 = 0.f, lrow1 = 0.f;

    uint32_t sQh = s2u(smem + QH), sKh = s2u(smem + KH), sVh = s2u(smem + VH);

    for (int mt = 0; mt < 16; ++mt) {
        int m0 = mt * 64;
        __syncthreads();
        {
            int d = tid >> 2, mc = (tid & 3) * 16;
            const __half* p = kb + (size_t)d * LCP + m0 + mc;
#pragma unroll
            for (int j = 0; j < 2; ++j) {
                uint4 v = *(const uint4*)(p + j * 8);
                const __half* hv = (const __half*)&v;
#pragma unroll
                for (int e = 0; e < 8; ++e)
                    *(__half*)(smem + KH + ((mc + j * 8 + e) * 72 + d) * 2) = hv[e];
            }
        }
        {
            int d = tid >> 2, mc = (tid & 3) * 16;
            const __half* p = vb + (size_t)d * LCP + m0 + mc;
#pragma unroll
            for (int j = 0; j < 2; ++j)
                *(uint4*)(smem + VH + (d * 72 + mc + j * 8) * 2) = *(const uint4*)(p + j * 8);
        }
        __syncthreads();

        float SA[8][4];
#pragma unroll
        for (int i = 0; i < 8; ++i)
#pragma unroll
            for (int e = 0; e < 4; ++e) SA[i][e] = 0.f;
#pragma unroll
        for (int kb_ = 0; kb_ < 4; ++kb_) {
            uint32_t ah[4];
            ldm4(ah, sQh + ((w * 16 + (lane & 15)) * 72 + kb_ * 16 + (lane >> 4) * 8) * 2);
#pragma unroll
            for (int g = 0; g < 4; ++g) {
                uint32_t bh_[4];
                ldm4(bh_, sKh + ((g * 16 + (lane & 7) + ((lane >> 4) & 1) * 8) * 72 +
                                 kb_ * 16 + ((lane >> 3) & 1) * 8) * 2);
#pragma unroll
                for (int jj = 0; jj < 2; ++jj)
                    mmah(SA[g * 2 + jj], ah, &bh_[jj * 2]);
            }
        }
#pragma unroll
        for (int ni = 0; ni < 8; ++ni) {
            SA[ni][0] *= 0.125f; SA[ni][1] *= 0.125f;
            SA[ni][2] *= 0.125f; SA[ni][3] *= 0.125f;
        }
        if (mt == 15 && (lane & 3) == 3) {
            SA[7][0] = SA[7][1] = SA[7][2] = SA[7][3] = -1e30f;
        }

        float mc0 = -1e30f, mc1 = -1e30f;
#pragma unroll
        for (int ni = 0; ni < 8; ++ni) {
            mc0 = fmaxf(mc0, fmaxf(SA[ni][0], SA[ni][1]));
            mc1 = fmaxf(mc1, fmaxf(SA[ni][2], SA[ni][3]));
        }
        mc0 = fmaxf(mc0, __shfl_xor_sync(0xffffffffu, mc0, 1));
        mc0 = fmaxf(mc0, __shfl_xor_sync(0xffffffffu, mc0, 2));
        mc1 = fmaxf(mc1, __shfl_xor_sync(0xffffffffu, mc1, 1));
        mc1 = fmaxf(mc1, __shfl_xor_sync(0xffffffffu, mc1, 2));
        float mn0 = fmaxf(mrow0, mc0), mn1 = fmaxf(mrow1, mc1);
        float a0 = __expf(mrow0 - mn0), a1 = __expf(mrow1 - mn1);
        mrow0 = mn0; mrow1 = mn1;
        float s0 = 0.f, s1 = 0.f;
#pragma unroll
        for (int ni = 0; ni < 8; ++ni) {
            SA[ni][0] = __expf(SA[ni][0] - mn0); s0 += SA[ni][0];
            SA[ni][1] = __expf(SA[ni][1] - mn0); s0 += SA[ni][1];
            SA[ni][2] = __expf(SA[ni][2] - mn1); s1 += SA[ni][2];
            SA[ni][3] = __expf(SA[ni][3] - mn1); s1 += SA[ni][3];
        }
        s0 += __shfl_xor_sync(0xffffffffu, s0, 1);
        s0 += __shfl_xor_sync(0xffffffffu, s0, 2);
        s1 += __shfl_xor_sync(0xffffffffu, s1, 1);
        s1 += __shfl_xor_sync(0xffffffffu, s1, 2);
        lrow0 = lrow0 * a0 + s0;
        lrow1 = lrow1 * a1 + s1;
#pragma unroll
        for (int ni = 0; ni < 8; ++ni) {
            OA[ni][0] *= a0; OA[ni][1] *= a0;
            OA[ni][2] *= a1; OA[ni][3] *= a1;
        }

#pragma unroll
        for (int t = 0; t < 4; ++t) {
            uint32_t aph[4];
            aph[0] = pkh(SA[2 * t][0], SA[2 * t][1]);
            aph[1] = pkh(SA[2 * t][2], SA[2 * t][3]);
            aph[2] = pkh(SA[2 * t + 1][0], SA[2 * t + 1][1]);
            aph[3] = pkh(SA[2 * t + 1][2], SA[2 * t + 1][3]);
#pragma unroll
            for (int g = 0; g < 4; ++g) {
                uint32_t bh_[4];
                ldm4(bh_, sVh + ((g * 16 + (lane & 7) + ((lane >> 4) & 1) * 8) * 72 +
                                 t * 16 + ((lane >> 3) & 1) * 8) * 2);
#pragma unroll
                for (int jj = 0; jj < 2; ++jj)
                    mmah(OA[g * 2 + jj], aph, &bh_[jj * 2]);
            }
        }
    }

    float i0 = 1.f / lrow0, i1 = 1.f / lrow1;
    int gr = lane >> 2, cl = lane & 3;
    int la = l0 + w * 16 + gr, lb2 = la + 8;
#pragma unroll
    for (int ni = 0; ni < 8; ++ni) {
        int d = ni * 8 + cl * 2;
        if (la < LC)
            sth2(g_c1h + ((size_t)bb * LC + la) * NKC + hh * DHH + d, OA[ni][0] * i0, OA[ni][1] * i0);
        if (lb2 < LC)
            sth2(g_c1h + ((size_t)bb * LC + lb2) * NKC + hh * DHH + d, OA[ni][2] * i1, OA[ni][3] * i1);
    }
}

// ================= generic HMMA GEMM (stages 5-9): 128x128, ring-3, f16-acc =================
template <int STG> struct Cfg {
    static constexpr int  NCH = (STG == 5) ? 16 : (STG == 6) ? 8 :
                                (STG == 7) ? 32 : (STG == 8) ? 16 : 32;
    static constexpr bool TRB = (STG == 7) || (STG == 8);
};

template <int STG>
__global__ void __launch_bounds__(256) gtc() {
    extern __shared__ __align__(128) char smem[];
    int tid = threadIdx.x, lane = tid & 31, wid = tid >> 5;
    int bx = blockIdx.x, by = blockIdx.y, z = blockIdx.z;
    int warpM = wid & 3, warpN = wid >> 2;

    auto issueA = [&](int c) {
        char* buf = smem + (c % 3) * BUFB;
        const __half* Ab = nullptr;
        long SAh = 0;
        int vrA = 128;
        if constexpr (STG == 5) {
            Ab = g_c1h + ((size_t)z * LC + bx * 128) * NKC + c * 32; SAh = NKC;
            int v = LC - bx * 128; vrA = v > 128 ? 128 : v;
        } else if constexpr (STG == 6) {
            Ab = g_w2h + (size_t)(bx * 128) * ADIM + c * 32; SAh = ADIM;
        } else if constexpr (STG == 7) {
            Ab = g_sch + ((size_t)z * NLB + bx * 128) * LCP + c * 32; SAh = LCP;
        } else if constexpr (STG == 8) {
            Ab = g_labh + (size_t)(bx * 128) * NKC + c * 32; SAh = NKC;
        } else {
            Ab = g_b2sh + ((size_t)z * NLB + bx * 128) * LCP + c * 32; SAh = LCP;
        }
        int r = tid >> 1, q = (tid & 1) * 2;
        int rc = (r < vrA) ? r : 0, sz = (r < vrA) ? 16 : 0;
        uint32_t d = s2u(buf) + r * 80 + q * 16;
        const __half* src = Ab + (size_t)rc * SAh + q * 8;
        cpa16z(d, src, sz);
        cpa16z(d + 16, src + 8, sz);
        if constexpr (!Cfg<STG>::TRB) {
            const __half* Bb = nullptr;
            long SBh = 0;
            int vrB = 128;
            if constexpr (STG == 5) {
                Bb = g_w1h + (size_t)(by * 128) * NKC + c * 32; SBh = NKC;
            } else if constexpr (STG == 6) {
                Bb = g_t1h + ((size_t)z * LC + by * 128) * ADIM + c * 32; SBh = ADIM;
                int v = LC - by * 128; vrB = v > 128 ? 128 : v;
            } else {
                Bb = g_v1h + ((size_t)(z * NKC + by * 128)) * LCP + c * 32; SBh = LCP;
            }
            uint32_t dB = s2u(buf + BHOFF);
#pragma unroll
            for (int qq = 0; qq < 2; ++qq) {
                int ca = tid + qq * 256, rb = ca >> 2, ch = ca & 3;
                int rbc = (rb < vrB) ? rb : 0, szb = (rb < vrB) ? 16 : 0;
                cpa16z(dB + rb * 80 + ch * 16, Bb + (size_t)rbc * SBh + ch * 8, szb);
            }
        }
        asm volatile("cp.async.commit_group;");
    };

    uint4 vbg[2] = {make_uint4(0,0,0,0), make_uint4(0,0,0,0)};
    auto gatherB = [&](int c) {
        int kk = tid >> 3, n0 = (tid & 7) * 8;
        if constexpr (STG == 7) {
            int l = c * 32 + kk;
            if (l < LC) {
                const __half* p = g_c1h + ((size_t)z * LC + l) * NKC + by * 128;
                vbg[0] = *(const uint4*)(p + n0);
                vbg[1] = *(const uint4*)(p + n0 + 64);
            } else {
                vbg[0] = vbg[1] = make_uint4(0, 0, 0, 0);
            }
        } else if constexpr (STG == 8) {
            const __half* p = g_k1h + ((size_t)(z * NKC + c * 32 + kk)) * LCP + by * 128;
            vbg[0] = *(const uint4*)(p + n0);
            vbg[1] = *(const uint4*)(p + n0 + 64);
        }
    };
    auto stashB = [&](char* buf) {
        int kk = tid >> 3, n0 = (tid & 7) * 8;
#pragma unroll
        for (int part = 0; part < 2; ++part) {
            const __half* hv = (const __half*)&vbg[part];
            int nb = n0 + part * 64;
#pragma unroll
            for (int e = 0; e < 8; ++e)
                *(__half*)(buf + BHOFF + ((nb + e) * 40 + kk) * 2) = hv[e];
        }
    };

    float acc[2][8][4];
    uint32_t hacc[2][8][2];
#pragma unroll
    for (int a = 0; a < 2; ++a)
#pragma unroll
        for (int b2 = 0; b2 < 8; ++b2) {
#pragma unroll
            for (int e = 0; e < 4; ++e) acc[a][b2][e] = 0.f;
            hacc[a][b2][0] = 0u; hacc[a][b2][1] = 0u;
        }

    constexpr int NCH = Cfg<STG>::NCH;
    if constexpr (Cfg<STG>::TRB) gatherB(0);
    issueA(0);
    issueA(1);
    for (int c = 0; c < NCH; ++c) {
        char* buf = smem + (c % 3) * BUFB;
        waitg(c + 1 >= NCH);
        if constexpr (Cfg<STG>::TRB) stashB(buf);
        __syncthreads();
        if (c + 2 < NCH) issueA(c + 2);
        if constexpr (Cfg<STG>::TRB) { if (c + 1 < NCH) gatherB(c + 1); }

        uint32_t sA = s2u(buf), sB = s2u(buf + BHOFF);
#pragma unroll
        for (int kb = 0; kb < 2; ++kb) {
            uint32_t ah[2][4];
#pragma unroll
            for (int mi = 0; mi < 2; ++mi)
                ldm4(ah[mi], sA + ((warpM * 32 + mi * 16 + (lane & 15)) * 40 +
                                   kb * 16 + (lane >> 4) * 8) * 2);
            uint32_t bh[4][4];
#pragma unroll
            for (int g = 0; g < 4; ++g)
                ldm4(bh[g], sB + ((warpN * 64 + g * 16 + (lane & 7) + ((lane >> 4) & 1) * 8) * 40 +
                                  kb * 16 + ((lane >> 3) & 1) * 8) * 2);
#pragma unroll
            for (int mi = 0; mi < 2; ++mi)
#pragma unroll
                for (int ni = 0; ni < 8; ++ni)
                    mmah16(hacc[mi][ni], ah[mi], &bh[ni >> 1][(ni & 1) * 2]);
        }
        if ((c & 1) == 1) promote(acc, hacc);
    }

    int r0 = lane >> 2, c0 = (lane & 3) * 2;
#pragma unroll
    for (int mi = 0; mi < 2; ++mi)
#pragma unroll
        for (int rh = 0; rh < 2; ++rh) {
            int m = warpM * 32 + mi * 16 + r0 + rh * 8;
#pragma unroll
            for (int ni = 0; ni < 8; ++ni) {
                int col = warpN * 64 + ni * 8 + c0;
                float v0 = acc[mi][ni][rh * 2 + 0];
                float v1 = acc[mi][ni][rh * 2 + 1];
                if constexpr (STG == 5) {
                    int l = bx * 128 + m;
                    if (l < LC)
                        sth2(g_t1h + ((size_t)z * LC + l) * ADIM + by * 128 + col,
                             tanhf(v0), tanhf(v1));
                } else if constexpr (STG == 6) {
                    int v = LC - by * 128; int vmax = v > 128 ? 128 : v;
                    if (col < vmax)
                        sth2(g_sch + ((size_t)z * NLB + bx * 128 + m) * LCP + by * 128 + col, v0, v1);
                } else if constexpr (STG == 7) {
                    *(float2*)(g_o1 + ((size_t)z * NLB + bx * 128 + m) * NKC + by * 128 + col) =
                        make_float2(v0, v1);
                } else if constexpr (STG == 8) {
                    int v = LC - by * 128; int vmax = v > 128 ? 128 : v;
                    if (col < vmax)
                        sth2(g_b2sh + ((size_t)z * NLB + bx * 128 + m) * LCP + by * 128 + col, v0, v1);
                } else {
                    *(float2*)(g_o2 + ((size_t)z * NLB + bx * 128 + m) * NKC + by * 128 + col) =
                        make_float2(v0, v1);
                }
            }
        }
}

// ---------- softmax over fp16 rows of length 1022 (stride 1024) ----------
__global__ void softmax_kernel(int sel) {
    __half* base = (sel == 1) ? g_sch : g_b2sh;
    __half* row = base + ((size_t)blockIdx.y * 1024 + blockIdx.x) * 1024;
    int tid = threadIdx.x;
    float v[4];
    float mx = -1e30f;
#pragma unroll
    for (int j = 0; j < 4; ++j) {
        int idx = tid + j * 256;
        v[j] = (idx < LC) ? __half2float(row[idx]) : -1e30f;
        mx = fmaxf(mx, v[j]);
    }
    __shared__ float red[256];
    red[tid] = mx; __syncthreads();
    for (int s = 128; s > 0; s >>= 1) { if (tid < s) red[tid] = fmaxf(red[tid], red[tid + s]); __syncthreads(); }
    mx = red[0]; __syncthreads();
    float sum = 0.f;
#pragma unroll
    for (int j = 0; j < 4; ++j) {
        int idx = tid + j * 256;
        v[j] = (idx < LC) ? __expf(v[j] - mx) : 0.f;
        sum += v[j];
    }
    red[tid] = sum; __syncthreads();
    for (int s = 128; s > 0; s >>= 1) { if (tid < s) red[tid] += red[tid + s]; __syncthreads(); }
    float inv = 1.f / red[0];
#pragma unroll
    for (int j = 0; j < 4; ++j) {
        int idx = tid + j * 256;
        if (idx < LC) row[idx] = __float2half_rn(v[j] * inv);
    }
}

// ---------- l2norm + concat ----------
__global__ void l2norm_kernel(float* __restrict__ out) {
    int row = blockIdx.x;
    const float* src = ((blockIdx.y == 0) ? g_o1 : g_o2) + (size_t)row * NKC;
    int tid = threadIdx.x;
    float4 v = ((const float4*)src)[tid];
    float ss = v.x * v.x + v.y * v.y + v.z * v.z + v.w * v.w;
    __shared__ float red[128];
    red[tid] = ss; __syncthreads();
    for (int s = 64; s > 0; s >>= 1) { if (tid < s) red[tid] += red[tid + s]; __syncthreads(); }
    float inv = 1.f / fmaxf(sqrtf(red[0]), 1e-12f);
    ((float4*)(out + (size_t)row * 1024 + blockIdx.y * NKC))[tid] =
        make_float4(v.x * inv, v.y * inv, v.z * inv, v.w * inv);
}

// ---------- launch ----------
extern "C" void kernel_launch(void* const* d_in, const int* in_sizes, int n_in,
                              void* d_out, int out_size) {
    (void)in_sizes; (void)n_in; (void)out_size;
    const float* emb = (const float*)d_in[0];
    const float* lab = (const float*)d_in[1];
    const float* wq  = (const float*)d_in[2];
    const float* bq  = (const float*)d_in[3];
    const float* wk  = (const float*)d_in[4];
    const float* bk  = (const float*)d_in[5];
    const float* wv  = (const float*)d_in[6];
    const float* bv  = (const float*)d_in[7];
    const float* w1  = (const float*)d_in[8];
    const float* w2  = (const float*)d_in[9];
    float* out = (float*)d_out;

    cudaFuncSetAttribute(convtc<0>, cudaFuncAttributeMaxDynamicSharedMemorySize, SMEMB);
    cudaFuncSetAttribute(convtc<1>, cudaFuncAttributeMaxDynamicSharedMemorySize, SMEMB);
    cudaFuncSetAttribute(convtc<2>, cudaFuncAttributeMaxDynamicSharedMemorySize, SMEMB);
    cudaFuncSetAttribute(gtc<5>, cudaFuncAttributeMaxDynamicSharedMemorySize, SMEMB);
    cudaFuncSetAttribute(gtc<6>, cudaFuncAttributeMaxDynamicSharedMemorySize, SMEMB);
    cudaFuncSetAttribute(gtc<7>, cudaFuncAttributeMaxDynamicSharedMemorySize, SMEMB);
    cudaFuncSetAttribute(gtc<8>, cudaFuncAttributeMaxDynamicSharedMemorySize, SMEMB);
    cudaFuncSetAttribute(gtc<9>, cudaFuncAttributeMaxDynamicSharedMemorySize, SMEMB);
    cudaFuncSetAttribute(flash_attn, cudaFuncAttributeMaxDynamicSharedMemorySize, FSM);

    dim3 thr(256);
    split_emb<<<8192, 256>>>(emb);
    repack_w_all<<<1024, 256>>>(wq, wk, wv);
    cvt_misc<<<512, 256>>>(lab, w1, w2);
    convtc<0><<<dim3(4, 8, 16), thr, SMEMB>>>(bq);
    convtc<1><<<dim3(4, 8, 16), thr, SMEMB>>>(bk);
    convtc<2><<<dim3(4, 8, 16), thr, SMEMB>>>(bv);

    flash_attn<<<dim3(8, 128), thr, FSM>>>();

    gtc<5><<<dim3(8, 2, 16), thr, SMEMB>>>();
    gtc<6><<<dim3(8, 8, 16), thr, SMEMB>>>();
    softmax_kernel<<<dim3(1024, 16), thr>>>(1);
    gtc<7><<<dim3(8, 4, 16), thr, SMEMB>>>();

    gtc<8><<<dim3(8, 8, 16), thr, SMEMB>>>();
    softmax_kernel<<<dim3(1024, 16), thr>>>(2);
    gtc<9><<<dim3(8, 4, 16), thr, SMEMB>>>();

    l2norm_kernel<<<dim3(16384, 2), dim3(128)>>>(out);
}

// round 15
// speedup vs baseline: 1.1732x; 1.1732x over previous
#include <cuda_runtime.h>
#include <cuda_fp16.h>
#include <cstdint>

#define BB    16
#define LSEQ  1024
#define DIN   512
#define NKC   512
#define HH    8
#define DHH   64
#define LC    1022
#define LCP   1024
#define NLB   1024
#define ADIM  256

// ---------- scratch (zero-init; pads never written) ----------
__device__ float g_o1[BB * NLB * NKC];
__device__ float g_o2[BB * NLB * NKC];
__device__ __align__(16) __half g_q1h[BB * NKC * LCP];
__device__ __align__(16) __half g_k1h[BB * NKC * LCP];
__device__ __align__(16) __half g_v1h[BB * NKC * LCP];
__device__ __align__(16) __half g_c1h[BB * LC * NKC];
__device__ __align__(16) __half g_t1h[BB * LC * ADIM];
__device__ __align__(16) __half g_sch[BB * NLB * LCP];
__device__ __align__(16) __half g_b2sh[BB * NLB * LCP];
__device__ __align__(16) __half g_ebh[BB * LSEQ * DIN];
__device__ __align__(16) __half g_wh[3][3 * NKC * DIN];
__device__ __align__(16) __half g_labh[NLB * NKC];
__device__ __align__(16) __half g_w1h[ADIM * NKC];
__device__ __align__(16) __half g_w2h[NLB * ADIM];

// ---------- smem: 3-buffer ring, per buffer A(10240) B(10240) ----------
#define BHOFF 10240
#define BUFB  20480
#define SMEMB (3 * BUFB)

__device__ __forceinline__ uint32_t s2u(const void* p) {
    uint32_t a;
    asm("{ .reg .u64 t; cvta.to.shared.u64 t, %1; cvt.u32.u64 %0, t; }" : "=r"(a) : "l"(p));
    return a;
}
__device__ __forceinline__ void ldm4(uint32_t* r, uint32_t addr) {
    asm volatile("ldmatrix.sync.aligned.m8n8.x4.shared.b16 {%0,%1,%2,%3}, [%4];"
                 : "=r"(r[0]), "=r"(r[1]), "=r"(r[2]), "=r"(r[3]) : "r"(addr));
}
__device__ __forceinline__ void mmah(float* c, const uint32_t* a, const uint32_t* b) {
    asm volatile("mma.sync.aligned.m16n8k16.row.col.f32.f16.f16.f32 "
                 "{%0,%1,%2,%3}, {%4,%5,%6,%7}, {%8,%9}, {%0,%1,%2,%3};"
                 : "+f"(c[0]), "+f"(c[1]), "+f"(c[2]), "+f"(c[3])
                 : "r"(a[0]), "r"(a[1]), "r"(a[2]), "r"(a[3]), "r"(b[0]), "r"(b[1]));
}
__device__ __forceinline__ void cpa16z(uint32_t d, const void* s, int sz) {
    asm volatile("cp.async.cg.shared.global [%0], [%1], 16, %2;" :: "r"(d), "l"(s), "r"(sz));
}
__device__ __forceinline__ void waitg(bool last) {
    if (last) asm volatile("cp.async.wait_group 0;");
    else      asm volatile("cp.async.wait_group 1;");
}

__device__ __forceinline__ uint32_t h2u(__half2 v) { return *reinterpret_cast<uint32_t*>(&v); }
__device__ __forceinline__ uint32_t pkh(float x, float y) {
    __half2 h = __floats2half2_rn(x, y);
    return h2u(h);
}
__device__ __forceinline__ uint2 cvt4hi(float4 v) {
    return make_uint2(h2u(__floats2half2_rn(v.x, v.y)), h2u(__floats2half2_rn(v.z, v.w)));
}
__device__ __forceinline__ void sth2(__half* p, float x, float y) {
    *(__half2*)p = __floats2half2_rn(x, y);
}

// ---------- input conversion kernels ----------
__global__ void split_emb(const float* __restrict__ e) {
    size_t i = ((size_t)blockIdx.x * 256 + threadIdx.x) * 4;
    *(uint2*)(g_ebh + i) = cvt4hi(*(const float4*)(e + i));
}
__global__ void repack_w_all(const float* __restrict__ wq, const float* __restrict__ wk,
                             const float* __restrict__ wv) {
    int idx = blockIdx.x * 256 + threadIdx.x;
    const float* ws[3] = {wq, wk, wv};
#pragma unroll
    for (int wsel = 0; wsel < 3; ++wsel)
#pragma unroll
        for (int t = 0; t < 3; ++t)
            g_wh[wsel][t * NKC * DIN + idx] = __float2half_rn(ws[wsel][idx * 3 + t]);
}
__global__ void cvt_misc(const float* __restrict__ lab, const float* __restrict__ w1,
                         const float* __restrict__ w2) {
    int i = blockIdx.x * 256 + threadIdx.x;
    if (i < 131072) *(uint2*)(g_labh + i * 4) = cvt4hi(((const float4*)lab)[i]);
    if (i < 32768)  *(uint2*)(g_w1h + i * 4) = cvt4hi(((const float4*)w1)[i]);
    if (i < 65536)  *(uint2*)(g_w2h + i * 4) = cvt4hi(((const float4*)w2)[i]);
}

// ================= conv: 128x128 tile, ring-3, ALL THREE convs in one launch =================
__global__ void __launch_bounds__(256, 2) convtc(const float* __restrict__ bq,
                                                 const float* __restrict__ bk,
                                                 const float* __restrict__ bv) {
    extern __shared__ __align__(128) char smem[];
    int tid = threadIdx.x, lane = tid & 31, wid = tid >> 5;
    int bx = blockIdx.x, by = blockIdx.y;
    int zz = blockIdx.z;              // [0,48): conv = zz/16, batch = zz%16
    int W = zz >> 4, z = zz & 15;
    int warpM = wid & 3, warpN = wid >> 2;

    auto issue = [&](int c) {
        char* buf = smem + (c % 3) * BUFB;
        int t3 = c >> 4, i0 = (c & 15) * 32;
        const __half* Ah = g_wh[W] + (size_t)(t3 * NKC + bx * 128) * DIN + i0;
        uint32_t sA = s2u(buf), sB = s2u(buf + BHOFF);
#pragma unroll
        for (int q = 0; q < 2; ++q) {
            int ca = tid + q * 256, r = ca >> 2, ch = ca & 3;
            cpa16z(sA + r * 80 + ch * 16, Ah + (size_t)r * DIN + ch * 8, 16);
            int lrow = by * 128 + t3 + r;
            int sz = (lrow < LSEQ) ? 16 : 0;
            int lcl = (lrow < LSEQ) ? lrow : (LSEQ - 1);
            cpa16z(sB + r * 80 + ch * 16,
                   g_ebh + ((size_t)z * LSEQ + lcl) * DIN + i0 + ch * 8, sz);
        }
        asm volatile("cp.async.commit_group;");
    };

    float acc[2][8][4];
#pragma unroll
    for (int a = 0; a < 2; ++a)
#pragma unroll
        for (int b2 = 0; b2 < 8; ++b2)
#pragma unroll
            for (int e = 0; e < 4; ++e) acc[a][b2][e] = 0.f;

    issue(0);
    issue(1);
    for (int c = 0; c < 48; ++c) {
        waitg(c + 1 >= 48);
        __syncthreads();
        if (c + 2 < 48) issue(c + 2);
        char* buf = smem + (c % 3) * BUFB;
        uint32_t sA = s2u(buf), sB = s2u(buf + BHOFF);
#pragma unroll
        for (int kb = 0; kb < 2; ++kb) {
            uint32_t ah[2][4];
#pragma unroll
            for (int mi = 0; mi < 2; ++mi)
                ldm4(ah[mi], sA + ((warpM * 32 + mi * 16 + (lane & 15)) * 40 +
                                   kb * 16 + (lane >> 4) * 8) * 2);
            uint32_t bh[4][4];
#pragma unroll
            for (int g = 0; g < 4; ++g)
                ldm4(bh[g], sB + ((warpN * 64 + g * 16 + (lane & 7) + ((lane >> 4) & 1) * 8) * 40 +
                                  kb * 16 + ((lane >> 3) & 1) * 8) * 2);
#pragma unroll
            for (int mi = 0; mi < 2; ++mi)
#pragma unroll
                for (int ni = 0; ni < 8; ++ni)
                    mmah(acc[mi][ni], ah[mi], &bh[ni >> 1][(ni & 1) * 2]);
        }
    }

    __half* outp = (W == 0) ? g_q1h : (W == 1) ? g_k1h : g_v1h;
    const float* bias = (W == 0) ? bq : (W == 1) ? bk : bv;
    int r0 = lane >> 2, c0 = (lane & 3) * 2;
    int vm = LC - by * 128; if (vm > 128) vm = 128;
#pragma unroll
    for (int mi = 0; mi < 2; ++mi)
#pragma unroll
        for (int rh = 0; rh < 2; ++rh) {
            int m = warpM * 32 + mi * 16 + r0 + rh * 8;
            float bv2 = bias[bx * 128 + m];
            __half* dst = outp + ((size_t)z * NKC + bx * 128 + m) * LCP + by * 128;
#pragma unroll
            for (int ni = 0; ni < 8; ++ni) {
                int col = warpN * 64 + ni * 8 + c0;
                if (col < vm) {
                    float v0 = acc[mi][ni][rh * 2 + 0] + bv2;
                    float v1 = acc[mi][ni][rh * 2 + 1] + bv2;
                    v0 = v0 > 0.f ? v0 : (__expf(v0) - 1.f);
                    v1 = v1 > 0.f ? v1 : (__expf(v1) - 1.f);
                    sth2(dst + col, v0, v1);
                }
            }
        }
}

// ================= flash attention (unchanged, proven) =================
#define FSM 36864
__global__ void __launch_bounds__(256) flash_attn() {
    extern __shared__ __align__(128) char smem[];
    constexpr int QH = 0, KH = 18432, VH = 27648;
    int tid = threadIdx.x, lane = tid & 31, w = tid >> 5;
    int l0 = blockIdx.x * 128, z = blockIdx.y, bb = z >> 3, hh = z & 7;
    const __half* qb = g_q1h + ((size_t)(bb * NKC + hh * DHH)) * LCP;
    const __half* kb = g_k1h + ((size_t)(bb * NKC + hh * DHH)) * LCP;
    const __half* vb = g_v1h + ((size_t)(bb * NKC + hh * DHH)) * LCP;

    {
        int d = tid >> 2, lc = (tid & 3) * 32;
        const __half* p = qb + (size_t)d * LCP + l0 + lc;
#pragma unroll
        for (int j = 0; j < 4; ++j) {
            uint4 v = *(const uint4*)(p + j * 8);
            const __half* hv = (const __half*)&v;
#pragma unroll
            for (int e = 0; e < 8; ++e)
                *(__half*)(smem + QH + ((lc + j * 8 + e) * 72 + d) * 2) = hv[e];
        }
    }

    float OA[8][4];
#pragma unroll
    for (int i = 0; i < 8; ++i)
#pragma unroll
        for (int e = 0; e < 4; ++e) OA[i][e] = 0.f;
    float mrow0 = -1e30f, mrow1 = -1e30f, lrow0 = 0.f, lrow1 = 0.f;

    uint32_t sQh = s2u(smem + QH), sKh = s2u(smem + KH), sVh = s2u(smem + VH);

    for (int mt = 0; mt < 16; ++mt) {
        int m0 = mt * 64;
        __syncthreads();
        {
            int d = tid >> 2, mc = (tid & 3) * 16;
            const __half* p = kb + (size_t)d * LCP + m0 + mc;
#pragma unroll
            for (int j = 0; j < 2; ++j) {
                uint4 v = *(const uint4*)(p + j * 8);
                const __half* hv = (const __half*)&v;
#pragma unroll
                for (int e = 0; e < 8; ++e)
                    *(__half*)(smem + KH + ((mc + j * 8 + e) * 72 + d) * 2) = hv[e];
            }
        }
        {
            int d = tid >> 2, mc = (tid & 3) * 16;
            const __half* p = vb + (size_t)d * LCP + m0 + mc;
#pragma unroll
            for (int j = 0; j < 2; ++j)
                *(uint4*)(smem + VH + (d * 72 + mc + j * 8) * 2) = *(const uint4*)(p + j * 8);
        }
        __syncthreads();

        float SA[8][4];
#pragma unroll
        for (int i = 0; i < 8; ++i)
#pragma unroll
            for (int e = 0; e < 4; ++e) SA[i][e] = 0.f;
#pragma unroll
        for (int kb_ = 0; kb_ < 4; ++kb_) {
            uint32_t ah[4];
            ldm4(ah, sQh + ((w * 16 + (lane & 15)) * 72 + kb_ * 16 + (lane >> 4) * 8) * 2);
#pragma unroll
            for (int g = 0; g < 4; ++g) {
                uint32_t bh_[4];
                ldm4(bh_, sKh + ((g * 16 + (lane & 7) + ((lane >> 4) & 1) * 8) * 72 +
                                 kb_ * 16 + ((lane >> 3) & 1) * 8) * 2);
#pragma unroll
                for (int jj = 0; jj < 2; ++jj)
                    mmah(SA[g * 2 + jj], ah, &bh_[jj * 2]);
            }
        }
#pragma unroll
        for (int ni = 0; ni < 8; ++ni) {
            SA[ni][0] *= 0.125f; SA[ni][1] *= 0.125f;
            SA[ni][2] *= 0.125f; SA[ni][3] *= 0.125f;
        }
        if (mt == 15 && (lane & 3) == 3) {
            SA[7][0] = SA[7][1] = SA[7][2] = SA[7][3] = -1e30f;
        }

        float mc0 = -1e30f, mc1 = -1e30f;
#pragma unroll
        for (int ni = 0; ni < 8; ++ni) {
            mc0 = fmaxf(mc0, fmaxf(SA[ni][0], SA[ni][1]));
            mc1 = fmaxf(mc1, fmaxf(SA[ni][2], SA[ni][3]));
        }
        mc0 = fmaxf(mc0, __shfl_xor_sync(0xffffffffu, mc0, 1));
        mc0 = fmaxf(mc0, __shfl_xor_sync(0xffffffffu, mc0, 2));
        mc1 = fmaxf(mc1, __shfl_xor_sync(0xffffffffu, mc1, 1));
        mc1 = fmaxf(mc1, __shfl_xor_sync(0xffffffffu, mc1, 2));
        float mn0 = fmaxf(mrow0, mc0), mn1 = fmaxf(mrow1, mc1);
        float a0 = __expf(mrow0 - mn0), a1 = __expf(mrow1 - mn1);
        mrow0 = mn0; mrow1 = mn1;
        float s0 = 0.f, s1 = 0.f;
#pragma unroll
        for (int ni = 0; ni < 8; ++ni) {
            SA[ni][0] = __expf(SA[ni][0] - mn0); s0 += SA[ni][0];
            SA[ni][1] = __expf(SA[ni][1] - mn0); s0 += SA[ni][1];
            SA[ni][2] = __expf(SA[ni][2] - mn1); s1 += SA[ni][2];
            SA[ni][3] = __expf(SA[ni][3] - mn1); s1 += SA[ni][3];
        }
        s0 += __shfl_xor_sync(0xffffffffu, s0, 1);
        s0 += __shfl_xor_sync(0xffffffffu, s0, 2);
        s1 += __shfl_xor_sync(0xffffffffu, s1, 1);
        s1 += __shfl_xor_sync(0xffffffffu, s1, 2);
        lrow0 = lrow0 * a0 + s0;
        lrow1 = lrow1 * a1 + s1;
#pragma unroll
        for (int ni = 0; ni < 8; ++ni) {
            OA[ni][0] *= a0; OA[ni][1] *= a0;
            OA[ni][2] *= a1; OA[ni][3] *= a1;
        }

#pragma unroll
        for (int t = 0; t < 4; ++t) {
            uint32_t aph[4];
            aph[0] = pkh(SA[2 * t][0], SA[2 * t][1]);
            aph[1] = pkh(SA[2 * t][2], SA[2 * t][3]);
            aph[2] = pkh(SA[2 * t + 1][0], SA[2 * t + 1][1]);
            aph[3] = pkh(SA[2 * t + 1][2], SA[2 * t + 1][3]);
#pragma unroll
            for (int g = 0; g < 4; ++g) {
                uint32_t bh_[4];
                ldm4(bh_, sVh + ((g * 16 + (lane & 7) + ((lane >> 4) & 1) * 8) * 72 +
                                 t * 16 + ((lane >> 3) & 1) * 8) * 2);
#pragma unroll
                for (int jj = 0; jj < 2; ++jj)
                    mmah(OA[g * 2 + jj], aph, &bh_[jj * 2]);
            }
        }
    }

    float i0 = 1.f / lrow0, i1 = 1.f / lrow1;
    int gr = lane >> 2, cl = lane & 3;
    int la = l0 + w * 16 + gr, lb2 = la + 8;
#pragma unroll
    for (int ni = 0; ni < 8; ++ni) {
        int d = ni * 8 + cl * 2;
        if (la < LC)
            sth2(g_c1h + ((size_t)bb * LC + la) * NKC + hh * DHH + d, OA[ni][0] * i0, OA[ni][1] * i0);
        if (lb2 < LC)
            sth2(g_c1h + ((size_t)bb * LC + lb2) * NKC + hh * DHH + d, OA[ni][2] * i1, OA[ni][3] * i1);
    }
}

// ================= generic HMMA GEMM (stages 5-9): 128x128 tile, ring-3 =================
template <int STG> struct Cfg {
    static constexpr int  NCH = (STG == 5) ? 16 : (STG == 6) ? 8 :
                                (STG == 7) ? 32 : (STG == 8) ? 16 : 32;
    static constexpr bool TRB = (STG == 7) || (STG == 8);
};

template <int STG>
__global__ void __launch_bounds__(256, 2) gtc() {
    extern __shared__ __align__(128) char smem[];
    int tid = threadIdx.x, lane = tid & 31, wid = tid >> 5;
    int bx = blockIdx.x, by = blockIdx.y, z = blockIdx.z;
    int warpM = wid & 3, warpN = wid >> 2;

    auto issueA = [&](int c) {
        char* buf = smem + (c % 3) * BUFB;
        const __half* Ab = nullptr;
        long SAh = 0;
        int vrA = 128;
        if constexpr (STG == 5) {
            Ab = g_c1h + ((size_t)z * LC + bx * 128) * NKC + c * 32; SAh = NKC;
            int v = LC - bx * 128; vrA = v > 128 ? 128 : v;
        } else if constexpr (STG == 6) {
            Ab = g_w2h + (size_t)(bx * 128) * ADIM + c * 32; SAh = ADIM;
        } else if constexpr (STG == 7) {
            Ab = g_sch + ((size_t)z * NLB + bx * 128) * LCP + c * 32; SAh = LCP;
        } else if constexpr (STG == 8) {
            Ab = g_labh + (size_t)(bx * 128) * NKC + c * 32; SAh = NKC;
        } else {
            Ab = g_b2sh + ((size_t)z * NLB + bx * 128) * LCP + c * 32; SAh = LCP;
        }
        int r = tid >> 1, q = (tid & 1) * 2;
        int rc = (r < vrA) ? r : 0, sz = (r < vrA) ? 16 : 0;
        uint32_t d = s2u(buf) + r * 80 + q * 16;
        const __half* src = Ab + (size_t)rc * SAh + q * 8;
        cpa16z(d, src, sz);
        cpa16z(d + 16, src + 8, sz);
        if constexpr (!Cfg<STG>::TRB) {
            const __half* Bb = nullptr;
            long SBh = 0;
            int vrB = 128;
            if constexpr (STG == 5) {
                Bb = g_w1h + (size_t)(by * 128) * NKC + c * 32; SBh = NKC;
            } else if constexpr (STG == 6) {
                Bb = g_t1h + ((size_t)z * LC + by * 128) * ADIM + c * 32; SBh = ADIM;
                int v = LC - by * 128; vrB = v > 128 ? 128 : v;
            } else {
                Bb = g_v1h + ((size_t)(z * NKC + by * 128)) * LCP + c * 32; SBh = LCP;
            }
            uint32_t dB = s2u(buf + BHOFF);
#pragma unroll
            for (int qq = 0; qq < 2; ++qq) {
                int ca = tid + qq * 256, rb = ca >> 2, ch = ca & 3;
                int rbc = (rb < vrB) ? rb : 0, szb = (rb < vrB) ? 16 : 0;
                cpa16z(dB + rb * 80 + ch * 16, Bb + (size_t)rbc * SBh + ch * 8, szb);
            }
        }
        asm volatile("cp.async.commit_group;");
    };

    uint4 vbg[2] = {make_uint4(0,0,0,0), make_uint4(0,0,0,0)};
    auto gatherB = [&](int c) {
        int kk = tid >> 3, n0 = (tid & 7) * 8;
        if constexpr (STG == 7) {
            int l = c * 32 + kk;
            if (l < LC) {
                const __half* p = g_c1h + ((size_t)z * LC + l) * NKC + by * 128;
                vbg[0] = *(const uint4*)(p + n0);
                vbg[1] = *(const uint4*)(p + n0 + 64);
            } else {
                vbg[0] = vbg[1] = make_uint4(0, 0, 0, 0);
            }
        } else if constexpr (STG == 8) {
            const __half* p = g_k1h + ((size_t)(z * NKC + c * 32 + kk)) * LCP + by * 128;
            vbg[0] = *(const uint4*)(p + n0);
            vbg[1] = *(const uint4*)(p + n0 + 64);
        }
    };
    auto stashB = [&](char* buf) {
        int kk = tid >> 3, n0 = (tid & 7) * 8;
#pragma unroll
        for (int part = 0; part < 2; ++part) {
            const __half* hv = (const __half*)&vbg[part];
            int nb = n0 + part * 64;
#pragma unroll
            for (int e = 0; e < 8; ++e)
                *(__half*)(buf + BHOFF + ((nb + e) * 40 + kk) * 2) = hv[e];
        }
    };

    float acc[2][8][4];
#pragma unroll
    for (int a = 0; a < 2; ++a)
#pragma unroll
        for (int b2 = 0; b2 < 8; ++b2)
#pragma unroll
            for (int e = 0; e < 4; ++e) acc[a][b2][e] = 0.f;

    constexpr int NCH = Cfg<STG>::NCH;
    if constexpr (Cfg<STG>::TRB) gatherB(0);
    issueA(0);
    issueA(1);
    for (int c = 0; c < NCH; ++c) {
        char* buf = smem + (c % 3) * BUFB;
        waitg(c + 1 >= NCH);
        if constexpr (Cfg<STG>::TRB) stashB(buf);
        __syncthreads();
        if (c + 2 < NCH) issueA(c + 2);
        if constexpr (Cfg<STG>::TRB) { if (c + 1 < NCH) gatherB(c + 1); }

        uint32_t sA = s2u(buf), sB = s2u(buf + BHOFF);
#pragma unroll
        for (int kb = 0; kb < 2; ++kb) {
            uint32_t ah[2][4];
#pragma unroll
            for (int mi = 0; mi < 2; ++mi)
                ldm4(ah[mi], sA + ((warpM * 32 + mi * 16 + (lane & 15)) * 40 +
                                   kb * 16 + (lane >> 4) * 8) * 2);
            uint32_t bh[4][4];
#pragma unroll
            for (int g = 0; g < 4; ++g)
                ldm4(bh[g], sB + ((warpN * 64 + g * 16 + (lane & 7) + ((lane >> 4) & 1) * 8) * 40 +
                                  kb * 16 + ((lane >> 3) & 1) * 8) * 2);
#pragma unroll
            for (int mi = 0; mi < 2; ++mi)
#pragma unroll
                for (int ni = 0; ni < 8; ++ni)
                    mmah(acc[mi][ni], ah[mi], &bh[ni >> 1][(ni & 1) * 2]);
        }
    }

    int r0 = lane >> 2, c0 = (lane & 3) * 2;
#pragma unroll
    for (int mi = 0; mi < 2; ++mi)
#pragma unroll
        for (int rh = 0; rh < 2; ++rh) {
            int m = warpM * 32 + mi * 16 + r0 + rh * 8;
#pragma unroll
            for (int ni = 0; ni < 8; ++ni) {
                int col = warpN * 64 + ni * 8 + c0;
                float v0 = acc[mi][ni][rh * 2 + 0];
                float v1 = acc[mi][ni][rh * 2 + 1];
                if constexpr (STG == 5) {
                    int l = bx * 128 + m;
                    if (l < LC)
                        sth2(g_t1h + ((size_t)z * LC + l) * ADIM + by * 128 + col,
                             tanhf(v0), tanhf(v1));
                } else if constexpr (STG == 6) {
                    int v = LC - by * 128; int vmax = v > 128 ? 128 : v;
                    if (col < vmax)
                        sth2(g_sch + ((size_t)z * NLB + bx * 128 + m) * LCP + by * 128 + col, v0, v1);
                } else if constexpr (STG == 7) {
                    *(float2*)(g_o1 + ((size_t)z * NLB + bx * 128 + m) * NKC + by * 128 + col) =
                        make_float2(v0, v1);
                } else if constexpr (STG == 8) {
                    int v = LC - by * 128; int vmax = v > 128 ? 128 : v;
                    if (col < vmax)
                        sth2(g_b2sh + ((size_t)z * NLB + bx * 128 + m) * LCP + by * 128 + col, v0, v1);
                } else {
                    *(float2*)(g_o2 + ((size_t)z * NLB + bx * 128 + m) * NKC + by * 128 + col) =
                        make_float2(v0, v1);
                }
            }
        }
}

// ---------- softmax over fp16 rows; one launch covers BOTH score tensors ----------
__global__ void softmax_kernel() {
    int zy = blockIdx.y;                  // [0,32): tensor = zy/16, batch = zy%16
    __half* base = (zy < 16) ? g_sch : g_b2sh;
    __half* row = base + ((size_t)(zy & 15) * 1024 + blockIdx.x) * 1024;
    int tid = threadIdx.x;
    float v[4];
    float mx = -1e30f;
#pragma unroll
    for (int j = 0; j < 4; ++j) {
        int idx = tid + j * 256;
        v[j] = (idx < LC) ? __half2float(row[idx]) : -1e30f;
        mx = fmaxf(mx, v[j]);
    }
    __shared__ float red[256];
    red[tid] = mx; __syncthreads();
    for (int s = 128; s > 0; s >>= 1) { if (tid < s) red[tid] = fmaxf(red[tid], red[tid + s]); __syncthreads(); }
    mx = red[0]; __syncthreads();
    float sum = 0.f;
#pragma unroll
    for (int j = 0; j < 4; ++j) {
        int idx = tid + j * 256;
        v[j] = (idx < LC) ? __expf(v[j] - mx) : 0.f;
        sum += v[j];
    }
    red[tid] = sum; __syncthreads();
    for (int s = 128; s > 0; s >>= 1) { if (tid < s) red[tid] += red[tid + s]; __syncthreads(); }
    float inv = 1.f / red[0];
#pragma unroll
    for (int j = 0; j < 4; ++j) {
        int idx = tid + j * 256;
        if (idx < LC) row[idx] = __float2half_rn(v[j] * inv);
    }
}

// ---------- l2norm + concat ----------
__global__ void l2norm_kernel(float* __restrict__ out) {
    int row = blockIdx.x;
    const float* src = ((blockIdx.y == 0) ? g_o1 : g_o2) + (size_t)row * NKC;
    int tid = threadIdx.x;
    float4 v = ((const float4*)src)[tid];
    float ss = v.x * v.x + v.y * v.y + v.z * v.z + v.w * v.w;
    __shared__ float red[128];
    red[tid] = ss; __syncthreads();
    for (int s = 64; s > 0; s >>= 1) { if (tid < s) red[tid] += red[tid + s]; __syncthreads(); }
    float inv = 1.f / fmaxf(sqrtf(red[0]), 1e-12f);
    ((float4*)(out + (size_t)row * 1024 + blockIdx.y * NKC))[tid] =
        make_float4(v.x * inv, v.y * inv, v.z * inv, v.w * inv);
}

// ---------- launch ----------
extern "C" void kernel_launch(void* const* d_in, const int* in_sizes, int n_in,
                              void* d_out, int out_size) {
    (void)in_sizes; (void)n_in; (void)out_size;
    const float* emb = (const float*)d_in[0];
    const float* lab = (const float*)d_in[1];
    const float* wq  = (const float*)d_in[2];
    const float* bq  = (const float*)d_in[3];
    const float* wk  = (const float*)d_in[4];
    const float* bk  = (const float*)d_in[5];
    const float* wv  = (const float*)d_in[6];
    const float* bv  = (const float*)d_in[7];
    const float* w1  = (const float*)d_in[8];
    const float* w2  = (const float*)d_in[9];
    float* out = (float*)d_out;

    cudaFuncSetAttribute(convtc, cudaFuncAttributeMaxDynamicSharedMemorySize, SMEMB);
    cudaFuncSetAttribute(gtc<5>, cudaFuncAttributeMaxDynamicSharedMemorySize, SMEMB);
    cudaFuncSetAttribute(gtc<6>, cudaFuncAttributeMaxDynamicSharedMemorySize, SMEMB);
    cudaFuncSetAttribute(gtc<7>, cudaFuncAttributeMaxDynamicSharedMemorySize, SMEMB);
    cudaFuncSetAttribute(gtc<8>, cudaFuncAttributeMaxDynamicSharedMemorySize, SMEMB);
    cudaFuncSetAttribute(gtc<9>, cudaFuncAttributeMaxDynamicSharedMemorySize, SMEMB);
    cudaFuncSetAttribute(flash_attn, cudaFuncAttributeMaxDynamicSharedMemorySize, FSM);

    dim3 thr(256);
    split_emb<<<8192, 256>>>(emb);
    repack_w_all<<<1024, 256>>>(wq, wk, wv);
    cvt_misc<<<512, 256>>>(lab, w1, w2);
    convtc<<<dim3(4, 8, 48), thr, SMEMB>>>(bq, bk, bv);

    flash_attn<<<dim3(8, 128), thr, FSM>>>();

    gtc<5><<<dim3(8, 2, 16), thr, SMEMB>>>();
    gtc<6><<<dim3(8, 8, 16), thr, SMEMB>>>();
    gtc<8><<<dim3(8, 8, 16), thr, SMEMB>>>();
    softmax_kernel<<<dim3(1024, 32), thr>>>();
    gtc<7><<<dim3(8, 4, 16), thr, SMEMB>>>();
    gtc<9><<<dim3(8, 4, 16), thr, SMEMB>>>();

    l2norm_kernel<<<dim3(16384, 2), dim3(128)>>>(out);
}

// round 16
// speedup vs baseline: 1.1998x; 1.0226x over previous
#include <cuda_runtime.h>
#include <cuda_fp16.h>
#include <cstdint>

#define BB    16
#define LSEQ  1024
#define DIN   512
#define NKC   512
#define HH    8
#define DHH   64
#define LC    1022
#define LCP   1024
#define NLB   1024
#define ADIM  256

// ---------- scratch (zero-init; pads never written) ----------
__device__ float g_o1[BB * NLB * NKC];
__device__ float g_o2[BB * NLB * NKC];
__device__ __align__(16) __half g_q1h[BB * NKC * LCP];
__device__ __align__(16) __half g_k1h[BB * NKC * LCP];
__device__ __align__(16) __half g_v1h[BB * NKC * LCP];
__device__ __align__(16) __half g_c1h[BB * LC * NKC];
__device__ __align__(16) __half g_t1h[BB * LC * ADIM];
__device__ __align__(16) __half g_sch[BB * NLB * LCP];
__device__ __align__(16) __half g_b2sh[BB * NLB * LCP];
__device__ __align__(16) __half g_ebh[BB * LSEQ * DIN];
__device__ __align__(16) __half g_wh[3][3 * NKC * DIN];
__device__ __align__(16) __half g_labh[NLB * NKC];
__device__ __align__(16) __half g_w1h[ADIM * NKC];
__device__ __align__(16) __half g_w2h[NLB * ADIM];

// ---------- smem: 3-buffer ring, per buffer A(10240) B(10240) ----------
#define BHOFF 10240
#define BUFB  20480
#define SMEMB (3 * BUFB)

__device__ __forceinline__ uint32_t s2u(const void* p) {
    uint32_t a;
    asm("{ .reg .u64 t; cvta.to.shared.u64 t, %1; cvt.u32.u64 %0, t; }" : "=r"(a) : "l"(p));
    return a;
}
__device__ __forceinline__ void ldm4(uint32_t* r, uint32_t addr) {
    asm volatile("ldmatrix.sync.aligned.m8n8.x4.shared.b16 {%0,%1,%2,%3}, [%4];"
                 : "=r"(r[0]), "=r"(r[1]), "=r"(r[2]), "=r"(r[3]) : "r"(addr));
}
__device__ __forceinline__ void mmah(float* c, const uint32_t* a, const uint32_t* b) {
    asm volatile("mma.sync.aligned.m16n8k16.row.col.f32.f16.f16.f32 "
                 "{%0,%1,%2,%3}, {%4,%5,%6,%7}, {%8,%9}, {%0,%1,%2,%3};"
                 : "+f"(c[0]), "+f"(c[1]), "+f"(c[2]), "+f"(c[3])
                 : "r"(a[0]), "r"(a[1]), "r"(a[2]), "r"(a[3]), "r"(b[0]), "r"(b[1]));
}
__device__ __forceinline__ void cpa16z(uint32_t d, const void* s, int sz) {
    asm volatile("cp.async.cg.shared.global [%0], [%1], 16, %2;" :: "r"(d), "l"(s), "r"(sz));
}
__device__ __forceinline__ void waitg(bool last) {
    if (last) asm volatile("cp.async.wait_group 0;");
    else      asm volatile("cp.async.wait_group 1;");
}

__device__ __forceinline__ uint32_t h2u(__half2 v) { return *reinterpret_cast<uint32_t*>(&v); }
__device__ __forceinline__ uint32_t pkh(float x, float y) {
    __half2 h = __floats2half2_rn(x, y);
    return h2u(h);
}
__device__ __forceinline__ uint2 cvt4hi(float4 v) {
    return make_uint2(h2u(__floats2half2_rn(v.x, v.y)), h2u(__floats2half2_rn(v.z, v.w)));
}
__device__ __forceinline__ void sth2(__half* p, float x, float y) {
    *(__half2*)p = __floats2half2_rn(x, y);
}

// ---------- merged input conversion ----------
__global__ void prep_all(const float* __restrict__ e, const float* __restrict__ wq,
                         const float* __restrict__ wk, const float* __restrict__ wv,
                         const float* __restrict__ lab, const float* __restrict__ w1,
                         const float* __restrict__ w2) {
    int b = blockIdx.x, tid = threadIdx.x;
    if (b < 8192) {
        size_t i = ((size_t)b * 256 + tid) * 4;
        *(uint2*)(g_ebh + i) = cvt4hi(*(const float4*)(e + i));
    } else if (b < 9216) {
        int idx = (b - 8192) * 256 + tid;
        const float* ws[3] = {wq, wk, wv};
#pragma unroll
        for (int wsel = 0; wsel < 3; ++wsel)
#pragma unroll
            for (int t = 0; t < 3; ++t)
                g_wh[wsel][t * NKC * DIN + idx] = __float2half_rn(ws[wsel][idx * 3 + t]);
    } else {
        int i = (b - 9216) * 256 + tid;
        if (i < 131072) *(uint2*)(g_labh + i * 4) = cvt4hi(((const float4*)lab)[i]);
        if (i < 32768)  *(uint2*)(g_w1h + i * 4) = cvt4hi(((const float4*)w1)[i]);
        if (i < 65536)  *(uint2*)(g_w2h + i * 4) = cvt4hi(((const float4*)w2)[i]);
    }
}

// ================= conv: 128x128 tile, ring-3, all three convs in one launch =================
__global__ void __launch_bounds__(256, 2) convtc(const float* __restrict__ bq,
                                                 const float* __restrict__ bk,
                                                 const float* __restrict__ bv) {
    extern __shared__ __align__(128) char smem[];
    int tid = threadIdx.x, lane = tid & 31, wid = tid >> 5;
    int bx = blockIdx.x, by = blockIdx.y;
    int zz = blockIdx.z;
    int W = zz >> 4, z = zz & 15;
    int warpM = wid & 3, warpN = wid >> 2;

    auto issue = [&](int c) {
        char* buf = smem + (c % 3) * BUFB;
        int t3 = c >> 4, i0 = (c & 15) * 32;
        const __half* Ah = g_wh[W] + (size_t)(t3 * NKC + bx * 128) * DIN + i0;
        uint32_t sA = s2u(buf), sB = s2u(buf + BHOFF);
#pragma unroll
        for (int q = 0; q < 2; ++q) {
            int ca = tid + q * 256, r = ca >> 2, ch = ca & 3;
            cpa16z(sA + r * 80 + ch * 16, Ah + (size_t)r * DIN + ch * 8, 16);
            int lrow = by * 128 + t3 + r;
            int sz = (lrow < LSEQ) ? 16 : 0;
            int lcl = (lrow < LSEQ) ? lrow : (LSEQ - 1);
            cpa16z(sB + r * 80 + ch * 16,
                   g_ebh + ((size_t)z * LSEQ + lcl) * DIN + i0 + ch * 8, sz);
        }
        asm volatile("cp.async.commit_group;");
    };

    float acc[2][8][4];
#pragma unroll
    for (int a = 0; a < 2; ++a)
#pragma unroll
        for (int b2 = 0; b2 < 8; ++b2)
#pragma unroll
            for (int e = 0; e < 4; ++e) acc[a][b2][e] = 0.f;

    issue(0);
    issue(1);
    for (int c = 0; c < 48; ++c) {
        waitg(c + 1 >= 48);
        __syncthreads();
        if (c + 2 < 48) issue(c + 2);
        char* buf = smem + (c % 3) * BUFB;
        uint32_t sA = s2u(buf), sB = s2u(buf + BHOFF);
#pragma unroll
        for (int kb = 0; kb < 2; ++kb) {
            uint32_t ah[2][4];
#pragma unroll
            for (int mi = 0; mi < 2; ++mi)
                ldm4(ah[mi], sA + ((warpM * 32 + mi * 16 + (lane & 15)) * 40 +
                                   kb * 16 + (lane >> 4) * 8) * 2);
            uint32_t bh[4][4];
#pragma unroll
            for (int g = 0; g < 4; ++g)
                ldm4(bh[g], sB + ((warpN * 64 + g * 16 + (lane & 7) + ((lane >> 4) & 1) * 8) * 40 +
                                  kb * 16 + ((lane >> 3) & 1) * 8) * 2);
#pragma unroll
            for (int mi = 0; mi < 2; ++mi)
#pragma unroll
                for (int ni = 0; ni < 8; ++ni)
                    mmah(acc[mi][ni], ah[mi], &bh[ni >> 1][(ni & 1) * 2]);
        }
    }

    __half* outp = (W == 0) ? g_q1h : (W == 1) ? g_k1h : g_v1h;
    const float* bias = (W == 0) ? bq : (W == 1) ? bk : bv;
    int r0 = lane >> 2, c0 = (lane & 3) * 2;
    int vm = LC - by * 128; if (vm > 128) vm = 128;
#pragma unroll
    for (int mi = 0; mi < 2; ++mi)
#pragma unroll
        for (int rh = 0; rh < 2; ++rh) {
            int m = warpM * 32 + mi * 16 + r0 + rh * 8;
            float bv2 = bias[bx * 128 + m];
            __half* dst = outp + ((size_t)z * NKC + bx * 128 + m) * LCP + by * 128;
#pragma unroll
            for (int ni = 0; ni < 8; ++ni) {
                int col = warpN * 64 + ni * 8 + c0;
                if (col < vm) {
                    float v0 = acc[mi][ni][rh * 2 + 0] + bv2;
                    float v1 = acc[mi][ni][rh * 2 + 1] + bv2;
                    v0 = v0 > 0.f ? v0 : (__expf(v0) - 1.f);
                    v1 = v1 > 0.f ? v1 : (__expf(v1) - 1.f);
                    sth2(dst + col, v0, v1);
                }
            }
        }
}

// ================= flash attention (unchanged, proven) =================
#define FSM 36864
__global__ void __launch_bounds__(256) flash_attn() {
    extern __shared__ __align__(128) char smem[];
    constexpr int QH = 0, KH = 18432, VH = 27648;
    int tid = threadIdx.x, lane = tid & 31, w = tid >> 5;
    int l0 = blockIdx.x * 128, z = blockIdx.y, bb = z >> 3, hh = z & 7;
    const __half* qb = g_q1h + ((size_t)(bb * NKC + hh * DHH)) * LCP;
    const __half* kb = g_k1h + ((size_t)(bb * NKC + hh * DHH)) * LCP;
    const __half* vb = g_v1h + ((size_t)(bb * NKC + hh * DHH)) * LCP;

    {
        int d = tid >> 2, lc = (tid & 3) * 32;
        const __half* p = qb + (size_t)d * LCP + l0 + lc;
#pragma unroll
        for (int j = 0; j < 4; ++j) {
            uint4 v = *(const uint4*)(p + j * 8);
            const __half* hv = (const __half*)&v;
#pragma unroll
            for (int e = 0; e < 8; ++e)
                *(__half*)(smem + QH + ((lc + j * 8 + e) * 72 + d) * 2) = hv[e];
        }
    }

    float OA[8][4];
#pragma unroll
    for (int i = 0; i < 8; ++i)
#pragma unroll
        for (int e = 0; e < 4; ++e) OA[i][e] = 0.f;
    float mrow0 = -1e30f, mrow1 = -1e30f, lrow0 = 0.f, lrow1 = 0.f;

    uint32_t sQh = s2u(smem + QH), sKh = s2u(smem + KH), sVh = s2u(smem + VH);

    for (int mt = 0; mt < 16; ++mt) {
        int m0 = mt * 64;
        __syncthreads();
        {
            int d = tid >> 2, mc = (tid & 3) * 16;
            const __half* p = kb + (size_t)d * LCP + m0 + mc;
#pragma unroll
            for (int j = 0; j < 2; ++j) {
                uint4 v = *(const uint4*)(p + j * 8);
                const __half* hv = (const __half*)&v;
#pragma unroll
                for (int e = 0; e < 8; ++e)
                    *(__half*)(smem + KH + ((mc + j * 8 + e) * 72 + d) * 2) = hv[e];
            }
        }
        {
            int d = tid >> 2, mc = (tid & 3) * 16;
            const __half* p = vb + (size_t)d * LCP + m0 + mc;
#pragma unroll
            for (int j = 0; j < 2; ++j)
                *(uint4*)(smem + VH + (d * 72 + mc + j * 8) * 2) = *(const uint4*)(p + j * 8);
        }
        __syncthreads();

        float SA[8][4];
#pragma unroll
        for (int i = 0; i < 8; ++i)
#pragma unroll
            for (int e = 0; e < 4; ++e) SA[i][e] = 0.f;
#pragma unroll
        for (int kb_ = 0; kb_ < 4; ++kb_) {
            uint32_t ah[4];
            ldm4(ah, sQh + ((w * 16 + (lane & 15)) * 72 + kb_ * 16 + (lane >> 4) * 8) * 2);
#pragma unroll
            for (int g = 0; g < 4; ++g) {
                uint32_t bh_[4];
                ldm4(bh_, sKh + ((g * 16 + (lane & 7) + ((lane >> 4) & 1) * 8) * 72 +
                                 kb_ * 16 + ((lane >> 3) & 1) * 8) * 2);
#pragma unroll
                for (int jj = 0; jj < 2; ++jj)
                    mmah(SA[g * 2 + jj], ah, &bh_[jj * 2]);
            }
        }
#pragma unroll
        for (int ni = 0; ni < 8; ++ni) {
            SA[ni][0] *= 0.125f; SA[ni][1] *= 0.125f;
            SA[ni][2] *= 0.125f; SA[ni][3] *= 0.125f;
        }
        if (mt == 15 && (lane & 3) == 3) {
            SA[7][0] = SA[7][1] = SA[7][2] = SA[7][3] = -1e30f;
        }

        float mc0 = -1e30f, mc1 = -1e30f;
#pragma unroll
        for (int ni = 0; ni < 8; ++ni) {
            mc0 = fmaxf(mc0, fmaxf(SA[ni][0], SA[ni][1]));
            mc1 = fmaxf(mc1, fmaxf(SA[ni][2], SA[ni][3]));
        }
        mc0 = fmaxf(mc0, __shfl_xor_sync(0xffffffffu, mc0, 1));
        mc0 = fmaxf(mc0, __shfl_xor_sync(0xffffffffu, mc0, 2));
        mc1 = fmaxf(mc1, __shfl_xor_sync(0xffffffffu, mc1, 1));
        mc1 = fmaxf(mc1, __shfl_xor_sync(0xffffffffu, mc1, 2));
        float mn0 = fmaxf(mrow0, mc0), mn1 = fmaxf(mrow1, mc1);
        float a0 = __expf(mrow0 - mn0), a1 = __expf(mrow1 - mn1);
        mrow0 = mn0; mrow1 = mn1;
        float s0 = 0.f, s1 = 0.f;
#pragma unroll
        for (int ni = 0; ni < 8; ++ni) {
            SA[ni][0] = __expf(SA[ni][0] - mn0); s0 += SA[ni][0];
            SA[ni][1] = __expf(SA[ni][1] - mn0); s0 += SA[ni][1];
            SA[ni][2] = __expf(SA[ni][2] - mn1); s1 += SA[ni][2];
            SA[ni][3] = __expf(SA[ni][3] - mn1); s1 += SA[ni][3];
        }
        s0 += __shfl_xor_sync(0xffffffffu, s0, 1);
        s0 += __shfl_xor_sync(0xffffffffu, s0, 2);
        s1 += __shfl_xor_sync(0xffffffffu, s1, 1);
        s1 += __shfl_xor_sync(0xffffffffu, s1, 2);
        lrow0 = lrow0 * a0 + s0;
        lrow1 = lrow1 * a1 + s1;
#pragma unroll
        for (int ni = 0; ni < 8; ++ni) {
            OA[ni][0] *= a0; OA[ni][1] *= a0;
            OA[ni][2] *= a1; OA[ni][3] *= a1;
        }

#pragma unroll
        for (int t = 0; t < 4; ++t) {
            uint32_t aph[4];
            aph[0] = pkh(SA[2 * t][0], SA[2 * t][1]);
            aph[1] = pkh(SA[2 * t][2], SA[2 * t][3]);
            aph[2] = pkh(SA[2 * t + 1][0], SA[2 * t + 1][1]);
            aph[3] = pkh(SA[2 * t + 1][2], SA[2 * t + 1][3]);
#pragma unroll
            for (int g = 0; g < 4; ++g) {
                uint32_t bh_[4];
                ldm4(bh_, sVh + ((g * 16 + (lane & 7) + ((lane >> 4) & 1) * 8) * 72 +
                                 t * 16 + ((lane >> 3) & 1) * 8) * 2);
#pragma unroll
                for (int jj = 0; jj < 2; ++jj)
                    mmah(OA[g * 2 + jj], aph, &bh_[jj * 2]);
            }
        }
    }

    float i0 = 1.f / lrow0, i1 = 1.f / lrow1;
    int gr = lane >> 2, cl = lane & 3;
    int la = l0 + w * 16 + gr, lb2 = la + 8;
#pragma unroll
    for (int ni = 0; ni < 8; ++ni) {
        int d = ni * 8 + cl * 2;
        if (la < LC)
            sth2(g_c1h + ((size_t)bb * LC + la) * NKC + hh * DHH + d, OA[ni][0] * i0, OA[ni][1] * i0);
        if (lb2 < LC)
            sth2(g_c1h + ((size_t)bb * LC + lb2) * NKC + hh * DHH + d, OA[ni][2] * i1, OA[ni][3] * i1);
    }
}

// ================= generic HMMA GEMM body (stages 5-9) =================
template <int STG> struct Cfg {
    static constexpr int  NCH = (STG == 5) ? 16 : (STG == 6) ? 8 :
                                (STG == 7) ? 32 : (STG == 8) ? 16 : 32;
    static constexpr bool TRB = (STG == 7) || (STG == 8);
};

template <int STG>
__device__ __forceinline__ void gtc_body(int z) {
    extern __shared__ __align__(128) char smem[];
    int tid = threadIdx.x, lane = tid & 31, wid = tid >> 5;
    int bx = blockIdx.x, by = blockIdx.y;
    int warpM = wid & 3, warpN = wid >> 2;

    auto issueA = [&](int c) {
        char* buf = smem + (c % 3) * BUFB;
        const __half* Ab = nullptr;
        long SAh = 0;
        int vrA = 128;
        if constexpr (STG == 5) {
            Ab = g_c1h + ((size_t)z * LC + bx * 128) * NKC + c * 32; SAh = NKC;
            int v = LC - bx * 128; vrA = v > 128 ? 128 : v;
        } else if constexpr (STG == 6) {
            Ab = g_w2h + (size_t)(bx * 128) * ADIM + c * 32; SAh = ADIM;
        } else if constexpr (STG == 7) {
            Ab = g_sch + ((size_t)z * NLB + bx * 128) * LCP + c * 32; SAh = LCP;
        } else if constexpr (STG == 8) {
            Ab = g_labh + (size_t)(bx * 128) * NKC + c * 32; SAh = NKC;
        } else {
            Ab = g_b2sh + ((size_t)z * NLB + bx * 128) * LCP + c * 32; SAh = LCP;
        }
        int r = tid >> 1, q = (tid & 1) * 2;
        int rc = (r < vrA) ? r : 0, sz = (r < vrA) ? 16 : 0;
        uint32_t d = s2u(buf) + r * 80 + q * 16;
        const __half* src = Ab + (size_t)rc * SAh + q * 8;
        cpa16z(d, src, sz);
        cpa16z(d + 16, src + 8, sz);
        if constexpr (!Cfg<STG>::TRB) {
            const __half* Bb = nullptr;
            long SBh = 0;
            int vrB = 128;
            if constexpr (STG == 5) {
                Bb = g_w1h + (size_t)(by * 128) * NKC + c * 32; SBh = NKC;
            } else if constexpr (STG == 6) {
                Bb = g_t1h + ((size_t)z * LC + by * 128) * ADIM + c * 32; SBh = ADIM;
                int v = LC - by * 128; vrB = v > 128 ? 128 : v;
            } else {
                Bb = g_v1h + ((size_t)(z * NKC + by * 128)) * LCP + c * 32; SBh = LCP;
            }
            uint32_t dB = s2u(buf + BHOFF);
#pragma unroll
            for (int qq = 0; qq < 2; ++qq) {
                int ca = tid + qq * 256, rb = ca >> 2, ch = ca & 3;
                int rbc = (rb < vrB) ? rb : 0, szb = (rb < vrB) ? 16 : 0;
                cpa16z(dB + rb * 80 + ch * 16, Bb + (size_t)rbc * SBh + ch * 8, szb);
            }
        }
        asm volatile("cp.async.commit_group;");
    };

    uint4 vbg[2] = {make_uint4(0,0,0,0), make_uint4(0,0,0,0)};
    auto gatherB = [&](int c) {
        int kk = tid >> 3, n0 = (tid & 7) * 8;
        if constexpr (STG == 7) {
            int l = c * 32 + kk;
            if (l < LC) {
                const __half* p = g_c1h + ((size_t)z * LC + l) * NKC + by * 128;
                vbg[0] = *(const uint4*)(p + n0);
                vbg[1] = *(const uint4*)(p + n0 + 64);
            } else {
                vbg[0] = vbg[1] = make_uint4(0, 0, 0, 0);
            }
        } else if constexpr (STG == 8) {
            const __half* p = g_k1h + ((size_t)(z * NKC + c * 32 + kk)) * LCP + by * 128;
            vbg[0] = *(const uint4*)(p + n0);
            vbg[1] = *(const uint4*)(p + n0 + 64);
        }
    };
    auto stashB = [&](char* buf) {
        int kk = tid >> 3, n0 = (tid & 7) * 8;
#pragma unroll
        for (int part = 0; part < 2; ++part) {
            const __half* hv = (const __half*)&vbg[part];
            int nb = n0 + part * 64;
#pragma unroll
            for (int e = 0; e < 8; ++e)
                *(__half*)(buf + BHOFF + ((nb + e) * 40 + kk) * 2) = hv[e];
        }
    };

    float acc[2][8][4];
#pragma unroll
    for (int a = 0; a < 2; ++a)
#pragma unroll
        for (int b2 = 0; b2 < 8; ++b2)
#pragma unroll
            for (int e = 0; e < 4; ++e) acc[a][b2][e] = 0.f;

    constexpr int NCH = Cfg<STG>::NCH;
    if constexpr (Cfg<STG>::TRB) gatherB(0);
    issueA(0);
    issueA(1);
    for (int c = 0; c < NCH; ++c) {
        char* buf = smem + (c % 3) * BUFB;
        waitg(c + 1 >= NCH);
        if constexpr (Cfg<STG>::TRB) stashB(buf);
        __syncthreads();
        if (c + 2 < NCH) issueA(c + 2);
        if constexpr (Cfg<STG>::TRB) { if (c + 1 < NCH) gatherB(c + 1); }

        uint32_t sA = s2u(buf), sB = s2u(buf + BHOFF);
#pragma unroll
        for (int kb = 0; kb < 2; ++kb) {
            uint32_t ah[2][4];
#pragma unroll
            for (int mi = 0; mi < 2; ++mi)
                ldm4(ah[mi], sA + ((warpM * 32 + mi * 16 + (lane & 15)) * 40 +
                                   kb * 16 + (lane >> 4) * 8) * 2);
            uint32_t bh[4][4];
#pragma unroll
            for (int g = 0; g < 4; ++g)
                ldm4(bh[g], sB + ((warpN * 64 + g * 16 + (lane & 7) + ((lane >> 4) & 1) * 8) * 40 +
                                  kb * 16 + ((lane >> 3) & 1) * 8) * 2);
#pragma unroll
            for (int mi = 0; mi < 2; ++mi)
#pragma unroll
                for (int ni = 0; ni < 8; ++ni)
                    mmah(acc[mi][ni], ah[mi], &bh[ni >> 1][(ni & 1) * 2]);
        }
    }

    int r0 = lane >> 2, c0 = (lane & 3) * 2;
#pragma unroll
    for (int mi = 0; mi < 2; ++mi)
#pragma unroll
        for (int rh = 0; rh < 2; ++rh) {
            int m = warpM * 32 + mi * 16 + r0 + rh * 8;
#pragma unroll
            for (int ni = 0; ni < 8; ++ni) {
                int col = warpN * 64 + ni * 8 + c0;
                float v0 = acc[mi][ni][rh * 2 + 0];
                float v1 = acc[mi][ni][rh * 2 + 1];
                if constexpr (STG == 5) {
                    int l = bx * 128 + m;
                    if (l < LC)
                        sth2(g_t1h + ((size_t)z * LC + l) * ADIM + by * 128 + col,
                             tanhf(v0), tanhf(v1));
                } else if constexpr (STG == 6) {
                    int v = LC - by * 128; int vmax = v > 128 ? 128 : v;
                    if (col < vmax)
                        sth2(g_sch + ((size_t)z * NLB + bx * 128 + m) * LCP + by * 128 + col, v0, v1);
                } else if constexpr (STG == 7) {
                    *(float2*)(g_o1 + ((size_t)z * NLB + bx * 128 + m) * NKC + by * 128 + col) =
                        make_float2(v0, v1);
                } else if constexpr (STG == 8) {
                    int v = LC - by * 128; int vmax = v > 128 ? 128 : v;
                    if (col < vmax)
                        sth2(g_b2sh + ((size_t)z * NLB + bx * 128 + m) * LCP + by * 128 + col, v0, v1);
                } else {
                    *(float2*)(g_o2 + ((size_t)z * NLB + bx * 128 + m) * NKC + by * 128 + col) =
                        make_float2(v0, v1);
                }
            }
        }
}

__global__ void __launch_bounds__(256, 2) gtc5()  { gtc_body<5>(blockIdx.z); }
// stage 6 (z<16) and stage 8 (z>=16) in one launch
__global__ void __launch_bounds__(256, 2) gtc68() {
    if (blockIdx.z < 16) gtc_body<6>(blockIdx.z);
    else                 gtc_body<8>(blockIdx.z - 16);
}
// stage 7 (z<16) and stage 9 (z>=16) in one launch
__global__ void __launch_bounds__(256, 2) gtc79() {
    if (blockIdx.z < 16) gtc_body<7>(blockIdx.z);
    else                 gtc_body<9>(blockIdx.z - 16);
}

// ---------- softmax over fp16 rows; one launch covers BOTH score tensors ----------
__global__ void softmax_kernel() {
    int zy = blockIdx.y;
    __half* base = (zy < 16) ? g_sch : g_b2sh;
    __half* row = base + ((size_t)(zy & 15) * 1024 + blockIdx.x) * 1024;
    int tid = threadIdx.x;
    float v[4];
    float mx = -1e30f;
#pragma unroll
    for (int j = 0; j < 4; ++j) {
        int idx = tid + j * 256;
        v[j] = (idx < LC) ? __half2float(row[idx]) : -1e30f;
        mx = fmaxf(mx, v[j]);
    }
    __shared__ float red[256];
    red[tid] = mx; __syncthreads();
    for (int s = 128; s > 0; s >>= 1) { if (tid < s) red[tid] = fmaxf(red[tid], red[tid + s]); __syncthreads(); }
    mx = red[0]; __syncthreads();
    float sum = 0.f;
#pragma unroll
    for (int j = 0; j < 4; ++j) {
        int idx = tid + j * 256;
        v[j] = (idx < LC) ? __expf(v[j] - mx) : 0.f;
        sum += v[j];
    }
    red[tid] = sum; __syncthreads();
    for (int s = 128; s > 0; s >>= 1) { if (tid < s) red[tid] += red[tid + s]; __syncthreads(); }
    float inv = 1.f / red[0];
#pragma unroll
    for (int j = 0; j < 4; ++j) {
        int idx = tid + j * 256;
        if (idx < LC) row[idx] = __float2half_rn(v[j] * inv);
    }
}

// ---------- l2norm + concat ----------
__global__ void l2norm_kernel(float* __restrict__ out) {
    int row = blockIdx.x;
    const float* src = ((blockIdx.y == 0) ? g_o1 : g_o2) + (size_t)row * NKC;
    int tid = threadIdx.x;
    float4 v = ((const float4*)src)[tid];
    float ss = v.x * v.x + v.y * v.y + v.z * v.z + v.w * v.w;
    __shared__ float red[128];
    red[tid] = ss; __syncthreads();
    for (int s = 64; s > 0; s >>= 1) { if (tid < s) red[tid] += red[tid + s]; __syncthreads(); }
    float inv = 1.f / fmaxf(sqrtf(red[0]), 1e-12f);
    ((float4*)(out + (size_t)row * 1024 + blockIdx.y * NKC))[tid] =
        make_float4(v.x * inv, v.y * inv, v.z * inv, v.w * inv);
}

// ---------- launch ----------
extern "C" void kernel_launch(void* const* d_in, const int* in_sizes, int n_in,
                              void* d_out, int out_size) {
    (void)in_sizes; (void)n_in; (void)out_size;
    const float* emb = (const float*)d_in[0];
    const float* lab = (const float*)d_in[1];
    const float* wq  = (const float*)d_in[2];
    const float* bq  = (const float*)d_in[3];
    const float* wk  = (const float*)d_in[4];
    const float* bk  = (const float*)d_in[5];
    const float* wv  = (const float*)d_in[6];
    const float* bv  = (const float*)d_in[7];
    const float* w1  = (const float*)d_in[8];
    const float* w2  = (const float*)d_in[9];
    float* out = (float*)d_out;

    cudaFuncSetAttribute(convtc, cudaFuncAttributeMaxDynamicSharedMemorySize, SMEMB);
    cudaFuncSetAttribute(gtc5,  cudaFuncAttributeMaxDynamicSharedMemorySize, SMEMB);
    cudaFuncSetAttribute(gtc68, cudaFuncAttributeMaxDynamicSharedMemorySize, SMEMB);
    cudaFuncSetAttribute(gtc79, cudaFuncAttributeMaxDynamicSharedMemorySize, SMEMB);
    cudaFuncSetAttribute(flash_attn, cudaFuncAttributeMaxDynamicSharedMemorySize, FSM);

    dim3 thr(256);
    prep_all<<<9728, 256>>>(emb, wq, wk, wv, lab, w1, w2);
    convtc<<<dim3(4, 8, 48), thr, SMEMB>>>(bq, bk, bv);

    flash_attn<<<dim3(8, 128), thr, FSM>>>();

    gtc5<<<dim3(8, 2, 16), thr, SMEMB>>>();
    gtc68<<<dim3(8, 8, 32), thr, SMEMB>>>();
    softmax_kernel<<<dim3(1024, 32), thr>>>();
    gtc79<<<dim3(8, 4, 32), thr, SMEMB>>>();

    l2norm_kernel<<<dim3(16384, 2), dim3(128)>>>(out);
}

// round 17
// speedup vs baseline: 1.2016x; 1.0015x over previous
#include <cuda_runtime.h>
#include <cuda_fp16.h>
#include <cstdint>

#define BB    16
#define LSEQ  1024
#define DIN   512
#define NKC   512
#define HH    8
#define DHH   64
#define LC    1022
#define LCP   1024
#define NLB   1024
#define ADIM  256

// ---------- scratch (zero-init; pads never written) ----------
__device__ float g_o1[BB * NLB * NKC];
__device__ float g_o2[BB * NLB * NKC];
__device__ __align__(16) __half g_q1h[BB * NKC * LCP];
__device__ __align__(16) __half g_k1h[BB * NKC * LCP];
__device__ __align__(16) __half g_v1h[BB * NKC * LCP];
__device__ __align__(16) __half g_c1h[BB * LC * NKC];
__device__ __align__(16) __half g_t1h[BB * LC * ADIM];
__device__ __align__(16) __half g_sch[BB * NLB * LCP];
__device__ __align__(16) __half g_b2sh[BB * NLB * LCP];
__device__ __align__(16) __half g_ebh[BB * LSEQ * DIN];
__device__ __align__(16) __half g_wh[3][3 * NKC * DIN];
__device__ __align__(16) __half g_labh[NLB * NKC];
__device__ __align__(16) __half g_w1h[ADIM * NKC];
__device__ __align__(16) __half g_w2h[NLB * ADIM];

// ---------- smem: 3-buffer ring, per buffer A(10240) B(10240) ----------
#define BHOFF 10240
#define BUFB  20480
#define SMEMB (3 * BUFB)

__device__ __forceinline__ uint32_t s2u(const void* p) {
    uint32_t a;
    asm("{ .reg .u64 t; cvta.to.shared.u64 t, %1; cvt.u32.u64 %0, t; }" : "=r"(a) : "l"(p));
    return a;
}
__device__ __forceinline__ void ldm4(uint32_t* r, uint32_t addr) {
    asm volatile("ldmatrix.sync.aligned.m8n8.x4.shared.b16 {%0,%1,%2,%3}, [%4];"
                 : "=r"(r[0]), "=r"(r[1]), "=r"(r[2]), "=r"(r[3]) : "r"(addr));
}
__device__ __forceinline__ void mmah(float* c, const uint32_t* a, const uint32_t* b) {
    asm volatile("mma.sync.aligned.m16n8k16.row.col.f32.f16.f16.f32 "
                 "{%0,%1,%2,%3}, {%4,%5,%6,%7}, {%8,%9}, {%0,%1,%2,%3};"
                 : "+f"(c[0]), "+f"(c[1]), "+f"(c[2]), "+f"(c[3])
                 : "r"(a[0]), "r"(a[1]), "r"(a[2]), "r"(a[3]), "r"(b[0]), "r"(b[1]));
}
__device__ __forceinline__ void cpa16z(uint32_t d, const void* s, int sz) {
    asm volatile("cp.async.cg.shared.global [%0], [%1], 16, %2;" :: "r"(d), "l"(s), "r"(sz));
}
__device__ __forceinline__ void waitg(bool last) {
    if (last) asm volatile("cp.async.wait_group 0;");
    else      asm volatile("cp.async.wait_group 1;");
}

__device__ __forceinline__ uint32_t h2u(__half2 v) { return *reinterpret_cast<uint32_t*>(&v); }
__device__ __forceinline__ uint32_t pkh(float x, float y) {
    __half2 h = __floats2half2_rn(x, y);
    return h2u(h);
}
__device__ __forceinline__ uint2 cvt4hi(float4 v) {
    return make_uint2(h2u(__floats2half2_rn(v.x, v.y)), h2u(__floats2half2_rn(v.z, v.w)));
}
__device__ __forceinline__ void sth2(__half* p, float x, float y) {
    *(__half2*)p = __floats2half2_rn(x, y);
}

// ---------- merged input conversion ----------
__global__ void prep_all(const float* __restrict__ e, const float* __restrict__ wq,
                         const float* __restrict__ wk, const float* __restrict__ wv,
                         const float* __restrict__ lab, const float* __restrict__ w1,
                         const float* __restrict__ w2) {
    int b = blockIdx.x, tid = threadIdx.x;
    if (b < 8192) {
        size_t i = ((size_t)b * 256 + tid) * 4;
        *(uint2*)(g_ebh + i) = cvt4hi(*(const float4*)(e + i));
    } else if (b < 9216) {
        int idx = (b - 8192) * 256 + tid;
        const float* ws[3] = {wq, wk, wv};
#pragma unroll
        for (int wsel = 0; wsel < 3; ++wsel)
#pragma unroll
            for (int t = 0; t < 3; ++t)
                g_wh[wsel][t * NKC * DIN + idx] = __float2half_rn(ws[wsel][idx * 3 + t]);
    } else {
        int i = (b - 9216) * 256 + tid;
        if (i < 131072) *(uint2*)(g_labh + i * 4) = cvt4hi(((const float4*)lab)[i]);
        if (i < 32768)  *(uint2*)(g_w1h + i * 4) = cvt4hi(((const float4*)w1)[i]);
        if (i < 65536)  *(uint2*)(g_w2h + i * 4) = cvt4hi(((const float4*)w2)[i]);
    }
}

// ================= conv: 128x128 tile, ring-3, all three convs in one launch =================
__global__ void __launch_bounds__(256, 2) convtc(const float* __restrict__ bq,
                                                 const float* __restrict__ bk,
                                                 const float* __restrict__ bv) {
    extern __shared__ __align__(128) char smem[];
    int tid = threadIdx.x, lane = tid & 31, wid = tid >> 5;
    int bx = blockIdx.x, by = blockIdx.y;
    int zz = blockIdx.z;
    int W = zz >> 4, z = zz & 15;
    int warpM = wid & 3, warpN = wid >> 2;

    auto issue = [&](int c) {
        char* buf = smem + (c % 3) * BUFB;
        int t3 = c >> 4, i0 = (c & 15) * 32;
        const __half* Ah = g_wh[W] + (size_t)(t3 * NKC + bx * 128) * DIN + i0;
        uint32_t sA = s2u(buf), sB = s2u(buf + BHOFF);
#pragma unroll
        for (int q = 0; q < 2; ++q) {
            int ca = tid + q * 256, r = ca >> 2, ch = ca & 3;
            cpa16z(sA + r * 80 + ch * 16, Ah + (size_t)r * DIN + ch * 8, 16);
            int lrow = by * 128 + t3 + r;
            int sz = (lrow < LSEQ) ? 16 : 0;
            int lcl = (lrow < LSEQ) ? lrow : (LSEQ - 1);
            cpa16z(sB + r * 80 + ch * 16,
                   g_ebh + ((size_t)z * LSEQ + lcl) * DIN + i0 + ch * 8, sz);
        }
        asm volatile("cp.async.commit_group;");
    };

    float acc[2][8][4];
#pragma unroll
    for (int a = 0; a < 2; ++a)
#pragma unroll
        for (int b2 = 0; b2 < 8; ++b2)
#pragma unroll
            for (int e = 0; e < 4; ++e) acc[a][b2][e] = 0.f;

    issue(0);
    issue(1);
    for (int c = 0; c < 48; ++c) {
        waitg(c + 1 >= 48);
        __syncthreads();
        if (c + 2 < 48) issue(c + 2);
        char* buf = smem + (c % 3) * BUFB;
        uint32_t sA = s2u(buf), sB = s2u(buf + BHOFF);
#pragma unroll
        for (int kb = 0; kb < 2; ++kb) {
            uint32_t ah[2][4];
#pragma unroll
            for (int mi = 0; mi < 2; ++mi)
                ldm4(ah[mi], sA + ((warpM * 32 + mi * 16 + (lane & 15)) * 40 +
                                   kb * 16 + (lane >> 4) * 8) * 2);
            uint32_t bh[4][4];
#pragma unroll
            for (int g = 0; g < 4; ++g)
                ldm4(bh[g], sB + ((warpN * 64 + g * 16 + (lane & 7) + ((lane >> 4) & 1) * 8) * 40 +
                                  kb * 16 + ((lane >> 3) & 1) * 8) * 2);
#pragma unroll
            for (int mi = 0; mi < 2; ++mi)
#pragma unroll
                for (int ni = 0; ni < 8; ++ni)
                    mmah(acc[mi][ni], ah[mi], &bh[ni >> 1][(ni & 1) * 2]);
        }
    }

    __half* outp = (W == 0) ? g_q1h : (W == 1) ? g_k1h : g_v1h;
    const float* bias = (W == 0) ? bq : (W == 1) ? bk : bv;
    int r0 = lane >> 2, c0 = (lane & 3) * 2;
    int vm = LC - by * 128; if (vm > 128) vm = 128;
#pragma unroll
    for (int mi = 0; mi < 2; ++mi)
#pragma unroll
        for (int rh = 0; rh < 2; ++rh) {
            int m = warpM * 32 + mi * 16 + r0 + rh * 8;
            float bv2 = bias[bx * 128 + m];
            __half* dst = outp + ((size_t)z * NKC + bx * 128 + m) * LCP + by * 128;
#pragma unroll
            for (int ni = 0; ni < 8; ++ni) {
                int col = warpN * 64 + ni * 8 + c0;
                if (col < vm) {
                    float v0 = acc[mi][ni][rh * 2 + 0] + bv2;
                    float v1 = acc[mi][ni][rh * 2 + 1] + bv2;
                    v0 = v0 > 0.f ? v0 : (__expf(v0) - 1.f);
                    v1 = v1 > 0.f ? v1 : (__expf(v1) - 1.f);
                    sth2(dst + col, v0, v1);
                }
            }
        }
}

// ================= flash attention (unchanged, proven) =================
#define FSM 36864
__global__ void __launch_bounds__(256) flash_attn() {
    extern __shared__ __align__(128) char smem[];
    constexpr int QH = 0, KH = 18432, VH = 27648;
    int tid = threadIdx.x, lane = tid & 31, w = tid >> 5;
    int l0 = blockIdx.x * 128, z = blockIdx.y, bb = z >> 3, hh = z & 7;
    const __half* qb = g_q1h + ((size_t)(bb * NKC + hh * DHH)) * LCP;
    const __half* kb = g_k1h + ((size_t)(bb * NKC + hh * DHH)) * LCP;
    const __half* vb = g_v1h + ((size_t)(bb * NKC + hh * DHH)) * LCP;

    {
        int d = tid >> 2, lc = (tid & 3) * 32;
        const __half* p = qb + (size_t)d * LCP + l0 + lc;
#pragma unroll
        for (int j = 0; j < 4; ++j) {
            uint4 v = *(const uint4*)(p + j * 8);
            const __half* hv = (const __half*)&v;
#pragma unroll
            for (int e = 0; e < 8; ++e)
                *(__half*)(smem + QH + ((lc + j * 8 + e) * 72 + d) * 2) = hv[e];
        }
    }

    float OA[8][4];
#pragma unroll
    for (int i = 0; i < 8; ++i)
#pragma unroll
        for (int e = 0; e < 4; ++e) OA[i][e] = 0.f;
    float mrow0 = -1e30f, mrow1 = -1e30f, lrow0 = 0.f, lrow1 = 0.f;

    uint32_t sQh = s2u(smem + QH), sKh = s2u(smem + KH), sVh = s2u(smem + VH);

    for (int mt = 0; mt < 16; ++mt) {
        int m0 = mt * 64;
        __syncthreads();
        {
            int d = tid >> 2, mc = (tid & 3) * 16;
            const __half* p = kb + (size_t)d * LCP + m0 + mc;
#pragma unroll
            for (int j = 0; j < 2; ++j) {
                uint4 v = *(const uint4*)(p + j * 8);
                const __half* hv = (const __half*)&v;
#pragma unroll
                for (int e = 0; e < 8; ++e)
                    *(__half*)(smem + KH + ((mc + j * 8 + e) * 72 + d) * 2) = hv[e];
            }
        }
        {
            int d = tid >> 2, mc = (tid & 3) * 16;
            const __half* p = vb + (size_t)d * LCP + m0 + mc;
#pragma unroll
            for (int j = 0; j < 2; ++j)
                *(uint4*)(smem + VH + (d * 72 + mc + j * 8) * 2) = *(const uint4*)(p + j * 8);
        }
        __syncthreads();

        float SA[8][4];
#pragma unroll
        for (int i = 0; i < 8; ++i)
#pragma unroll
            for (int e = 0; e < 4; ++e) SA[i][e] = 0.f;
#pragma unroll
        for (int kb_ = 0; kb_ < 4; ++kb_) {
            uint32_t ah[4];
            ldm4(ah, sQh + ((w * 16 + (lane & 15)) * 72 + kb_ * 16 + (lane >> 4) * 8) * 2);
#pragma unroll
            for (int g = 0; g < 4; ++g) {
                uint32_t bh_[4];
                ldm4(bh_, sKh + ((g * 16 + (lane & 7) + ((lane >> 4) & 1) * 8) * 72 +
                                 kb_ * 16 + ((lane >> 3) & 1) * 8) * 2);
#pragma unroll
                for (int jj = 0; jj < 2; ++jj)
                    mmah(SA[g * 2 + jj], ah, &bh_[jj * 2]);
            }
        }
#pragma unroll
        for (int ni = 0; ni < 8; ++ni) {
            SA[ni][0] *= 0.125f; SA[ni][1] *= 0.125f;
            SA[ni][2] *= 0.125f; SA[ni][3] *= 0.125f;
        }
        if (mt == 15 && (lane & 3) == 3) {
            SA[7][0] = SA[7][1] = SA[7][2] = SA[7][3] = -1e30f;
        }

        float mc0 = -1e30f, mc1 = -1e30f;
#pragma unroll
        for (int ni = 0; ni < 8; ++ni) {
            mc0 = fmaxf(mc0, fmaxf(SA[ni][0], SA[ni][1]));
            mc1 = fmaxf(mc1, fmaxf(SA[ni][2], SA[ni][3]));
        }
        mc0 = fmaxf(mc0, __shfl_xor_sync(0xffffffffu, mc0, 1));
        mc0 = fmaxf(mc0, __shfl_xor_sync(0xffffffffu, mc0, 2));
        mc1 = fmaxf(mc1, __shfl_xor_sync(0xffffffffu, mc1, 1));
        mc1 = fmaxf(mc1, __shfl_xor_sync(0xffffffffu, mc1, 2));
        float mn0 = fmaxf(mrow0, mc0), mn1 = fmaxf(mrow1, mc1);
        float a0 = __expf(mrow0 - mn0), a1 = __expf(mrow1 - mn1);
        mrow0 = mn0; mrow1 = mn1;
        float s0 = 0.f, s1 = 0.f;
#pragma unroll
        for (int ni = 0; ni < 8; ++ni) {
            SA[ni][0] = __expf(SA[ni][0] - mn0); s0 += SA[ni][0];
            SA[ni][1] = __expf(SA[ni][1] - mn0); s0 += SA[ni][1];
            SA[ni][2] = __expf(SA[ni][2] - mn1); s1 += SA[ni][2];
            SA[ni][3] = __expf(SA[ni][3] - mn1); s1 += SA[ni][3];
        }
        s0 += __shfl_xor_sync(0xffffffffu, s0, 1);
        s0 += __shfl_xor_sync(0xffffffffu, s0, 2);
        s1 += __shfl_xor_sync(0xffffffffu, s1, 1);
        s1 += __shfl_xor_sync(0xffffffffu, s1, 2);
        lrow0 = lrow0 * a0 + s0;
        lrow1 = lrow1 * a1 + s1;
#pragma unroll
        for (int ni = 0; ni < 8; ++ni) {
            OA[ni][0] *= a0; OA[ni][1] *= a0;
            OA[ni][2] *= a1; OA[ni][3] *= a1;
        }

#pragma unroll
        for (int t = 0; t < 4; ++t) {
            uint32_t aph[4];
            aph[0] = pkh(SA[2 * t][0], SA[2 * t][1]);
            aph[1] = pkh(SA[2 * t][2], SA[2 * t][3]);
            aph[2] = pkh(SA[2 * t + 1][0], SA[2 * t + 1][1]);
            aph[3] = pkh(SA[2 * t + 1][2], SA[2 * t + 1][3]);
#pragma unroll
            for (int g = 0; g < 4; ++g) {
                uint32_t bh_[4];
                ldm4(bh_, sVh + ((g * 16 + (lane & 7) + ((lane >> 4) & 1) * 8) * 72 +
                                 t * 16 + ((lane >> 3) & 1) * 8) * 2);
#pragma unroll
                for (int jj = 0; jj < 2; ++jj)
                    mmah(OA[g * 2 + jj], aph, &bh_[jj * 2]);
            }
        }
    }

    float i0 = 1.f / lrow0, i1 = 1.f / lrow1;
    int gr = lane >> 2, cl = lane & 3;
    int la = l0 + w * 16 + gr, lb2 = la + 8;
#pragma unroll
    for (int ni = 0; ni < 8; ++ni) {
        int d = ni * 8 + cl * 2;
        if (la < LC)
            sth2(g_c1h + ((size_t)bb * LC + la) * NKC + hh * DHH + d, OA[ni][0] * i0, OA[ni][1] * i0);
        if (lb2 < LC)
            sth2(g_c1h + ((size_t)bb * LC + lb2) * NKC + hh * DHH + d, OA[ni][2] * i1, OA[ni][3] * i1);
    }
}

// ================= generic HMMA GEMM body (stages 5-9) =================
template <int STG> struct Cfg {
    static constexpr int  NCH = (STG == 5) ? 16 : (STG == 6) ? 8 :
                                (STG == 7) ? 32 : (STG == 8) ? 16 : 32;
    static constexpr bool TRB = (STG == 7) || (STG == 8);
};

template <int STG>
__device__ __forceinline__ void gtc_body(int z) {
    extern __shared__ __align__(128) char smem[];
    int tid = threadIdx.x, lane = tid & 31, wid = tid >> 5;
    int bx = blockIdx.x, by = blockIdx.y;
    int warpM = wid & 3, warpN = wid >> 2;

    auto issueA = [&](int c) {
        char* buf = smem + (c % 3) * BUFB;
        const __half* Ab = nullptr;
        long SAh = 0;
        int vrA = 128;
        if constexpr (STG == 5) {
            Ab = g_c1h + ((size_t)z * LC + bx * 128) * NKC + c * 32; SAh = NKC;
            int v = LC - bx * 128; vrA = v > 128 ? 128 : v;
        } else if constexpr (STG == 6) {
            Ab = g_w2h + (size_t)(bx * 128) * ADIM + c * 32; SAh = ADIM;
        } else if constexpr (STG == 7) {
            Ab = g_sch + ((size_t)z * NLB + bx * 128) * LCP + c * 32; SAh = LCP;
        } else if constexpr (STG == 8) {
            Ab = g_labh + (size_t)(bx * 128) * NKC + c * 32; SAh = NKC;
        } else {
            Ab = g_b2sh + ((size_t)z * NLB + bx * 128) * LCP + c * 32; SAh = LCP;
        }
        int r = tid >> 1, q = (tid & 1) * 2;
        int rc = (r < vrA) ? r : 0, sz = (r < vrA) ? 16 : 0;
        uint32_t d = s2u(buf) + r * 80 + q * 16;
        const __half* src = Ab + (size_t)rc * SAh + q * 8;
        cpa16z(d, src, sz);
        cpa16z(d + 16, src + 8, sz);
        if constexpr (!Cfg<STG>::TRB) {
            const __half* Bb = nullptr;
            long SBh = 0;
            int vrB = 128;
            if constexpr (STG == 5) {
                Bb = g_w1h + (size_t)(by * 128) * NKC + c * 32; SBh = NKC;
            } else if constexpr (STG == 6) {
                Bb = g_t1h + ((size_t)z * LC + by * 128) * ADIM + c * 32; SBh = ADIM;
                int v = LC - by * 128; vrB = v > 128 ? 128 : v;
            } else {
                Bb = g_v1h + ((size_t)(z * NKC + by * 128)) * LCP + c * 32; SBh = LCP;
            }
            uint32_t dB = s2u(buf + BHOFF);
#pragma unroll
            for (int qq = 0; qq < 2; ++qq) {
                int ca = tid + qq * 256, rb = ca >> 2, ch = ca & 3;
                int rbc = (rb < vrB) ? rb : 0, szb = (rb < vrB) ? 16 : 0;
                cpa16z(dB + rb * 80 + ch * 16, Bb + (size_t)rbc * SBh + ch * 8, szb);
            }
        }
        asm volatile("cp.async.commit_group;");
    };

    uint4 vbg[2] = {make_uint4(0,0,0,0), make_uint4(0,0,0,0)};
    auto gatherB = [&](int c) {
        int kk = tid >> 3, n0 = (tid & 7) * 8;
        if constexpr (STG == 7) {
            int l = c * 32 + kk;
            if (l < LC) {
                const __half* p = g_c1h + ((size_t)z * LC + l) * NKC + by * 128;
                vbg[0] = *(const uint4*)(p + n0);
                vbg[1] = *(const uint4*)(p + n0 + 64);
            } else {
                vbg[0] = vbg[1] = make_uint4(0, 0, 0, 0);
            }
        } else if constexpr (STG == 8) {
            const __half* p = g_k1h + ((size_t)(z * NKC + c * 32 + kk)) * LCP + by * 128;
            vbg[0] = *(const uint4*)(p + n0);
            vbg[1] = *(const uint4*)(p + n0 + 64);
        }
    };
    auto stashB = [&](char* buf) {
        int kk = tid >> 3, n0 = (tid & 7) * 8;
#pragma unroll
        for (int part = 0; part < 2; ++part) {
            const __half* hv = (const __half*)&vbg[part];
            int nb = n0 + part * 64;
#pragma unroll
            for (int e = 0; e < 8; ++e)
                *(__half*)(buf + BHOFF + ((nb + e) * 40 + kk) * 2) = hv[e];
        }
    };

    float acc[2][8][4];
#pragma unroll
    for (int a = 0; a < 2; ++a)
#pragma unroll
        for (int b2 = 0; b2 < 8; ++b2)
#pragma unroll
            for (int e = 0; e < 4; ++e) acc[a][b2][e] = 0.f;

    constexpr int NCH = Cfg<STG>::NCH;
    if constexpr (Cfg<STG>::TRB) gatherB(0);
    issueA(0);
    issueA(1);
    for (int c = 0; c < NCH; ++c) {
        char* buf = smem + (c % 3) * BUFB;
        waitg(c + 1 >= NCH);
        if constexpr (Cfg<STG>::TRB) stashB(buf);
        __syncthreads();
        if (c + 2 < NCH) issueA(c + 2);
        if constexpr (Cfg<STG>::TRB) { if (c + 1 < NCH) gatherB(c + 1); }

        uint32_t sA = s2u(buf), sB = s2u(buf + BHOFF);
#pragma unroll
        for (int kb = 0; kb < 2; ++kb) {
            uint32_t ah[2][4];
#pragma unroll
            for (int mi = 0; mi < 2; ++mi)
                ldm4(ah[mi], sA + ((warpM * 32 + mi * 16 + (lane & 15)) * 40 +
                                   kb * 16 + (lane >> 4) * 8) * 2);
            uint32_t bh[4][4];
#pragma unroll
            for (int g = 0; g < 4; ++g)
                ldm4(bh[g], sB + ((warpN * 64 + g * 16 + (lane & 7) + ((lane >> 4) & 1) * 8) * 40 +
                                  kb * 16 + ((lane >> 3) & 1) * 8) * 2);
#pragma unroll
            for (int mi = 0; mi < 2; ++mi)
#pragma unroll
                for (int ni = 0; ni < 8; ++ni)
                    mmah(acc[mi][ni], ah[mi], &bh[ni >> 1][(ni & 1) * 2]);
        }
    }

    int r0 = lane >> 2, c0 = (lane & 3) * 2;
#pragma unroll
    for (int mi = 0; mi < 2; ++mi)
#pragma unroll
        for (int rh = 0; rh < 2; ++rh) {
            int m = warpM * 32 + mi * 16 + r0 + rh * 8;
#pragma unroll
            for (int ni = 0; ni < 8; ++ni) {
                int col = warpN * 64 + ni * 8 + c0;
                float v0 = acc[mi][ni][rh * 2 + 0];
                float v1 = acc[mi][ni][rh * 2 + 1];
                if constexpr (STG == 5) {
                    int l = bx * 128 + m;
                    if (l < LC)
                        sth2(g_t1h + ((size_t)z * LC + l) * ADIM + by * 128 + col,
                             tanhf(v0), tanhf(v1));
                } else if constexpr (STG == 6) {
                    int v = LC - by * 128; int vmax = v > 128 ? 128 : v;
                    if (col < vmax)
                        sth2(g_sch + ((size_t)z * NLB + bx * 128 + m) * LCP + by * 128 + col, v0, v1);
                } else if constexpr (STG == 7) {
                    *(float2*)(g_o1 + ((size_t)z * NLB + bx * 128 + m) * NKC + by * 128 + col) =
                        make_float2(v0, v1);
                } else if constexpr (STG == 8) {
                    int v = LC - by * 128; int vmax = v > 128 ? 128 : v;
                    if (col < vmax)
                        sth2(g_b2sh + ((size_t)z * NLB + bx * 128 + m) * LCP + by * 128 + col, v0, v1);
                } else {
                    *(float2*)(g_o2 + ((size_t)z * NLB + bx * 128 + m) * NKC + by * 128 + col) =
                        make_float2(v0, v1);
                }
            }
        }
}

__global__ void __launch_bounds__(256, 2) gtc5()  { gtc_body<5>(blockIdx.z); }
// stage 6 (z<16) and stage 8 (z>=16) in one launch
__global__ void __launch_bounds__(256, 2) gtc68() {
    if (blockIdx.z < 16) gtc_body<6>(blockIdx.z);
    else                 gtc_body<8>(blockIdx.z - 16);
}
// stage 7 (z<16) and stage 9 (z>=16) in one launch
__global__ void __launch_bounds__(256, 2) gtc79() {
    if (blockIdx.z < 16) gtc_body<7>(blockIdx.z);
    else                 gtc_body<9>(blockIdx.z - 16);
}

// ---------- softmax over fp16 rows; one launch covers BOTH score tensors ----------
__global__ void softmax_kernel() {
    int zy = blockIdx.y;
    __half* base = (zy < 16) ? g_sch : g_b2sh;
    __half* row = base + ((size_t)(zy & 15) * 1024 + blockIdx.x) * 1024;
    int tid = threadIdx.x;
    float v[4];
    float mx = -1e30f;
#pragma unroll
    for (int j = 0; j < 4; ++j) {
        int idx = tid + j * 256;
        v[j] = (idx < LC) ? __half2float(row[idx]) : -1e30f;
        mx = fmaxf(mx, v[j]);
    }
    __shared__ float red[256];
    red[tid] = mx; __syncthreads();
    for (int s = 128; s > 0; s >>= 1) { if (tid < s) red[tid] = fmaxf(red[tid], red[tid + s]); __syncthreads(); }
    mx = red[0]; __syncthreads();
    float sum = 0.f;
#pragma unroll
    for (int j = 0; j < 4; ++j) {
        int idx = tid + j * 256;
        v[j] = (idx < LC) ? __expf(v[j] - mx) : 0.f;
        sum += v[j];
    }
    red[tid] = sum; __syncthreads();
    for (int s = 128; s > 0; s >>= 1) { if (tid < s) red[tid] += red[tid + s]; __syncthreads(); }
    float inv = 1.f / red[0];
#pragma unroll
    for (int j = 0; j < 4; ++j) {
        int idx = tid + j * 256;
        if (idx < LC) row[idx] = __float2half_rn(v[j] * inv);
    }
}

// ---------- l2norm + concat ----------
__global__ void l2norm_kernel(float* __restrict__ out) {
    int row = blockIdx.x;
    const float* src = ((blockIdx.y == 0) ? g_o1 : g_o2) + (size_t)row * NKC;
    int tid = threadIdx.x;
    float4 v = ((const float4*)src)[tid];
    float ss = v.x * v.x + v.y * v.y + v.z * v.z + v.w * v.w;
    __shared__ float red[128];
    red[tid] = ss; __syncthreads();
    for (int s = 64; s > 0; s >>= 1) { if (tid < s) red[tid] += red[tid + s]; __syncthreads(); }
    float inv = 1.f / fmaxf(sqrtf(red[0]), 1e-12f);
    ((float4*)(out + (size_t)row * 1024 + blockIdx.y * NKC))[tid] =
        make_float4(v.x * inv, v.y * inv, v.z * inv, v.w * inv);
}

// ---------- launch ----------
extern "C" void kernel_launch(void* const* d_in, const int* in_sizes, int n_in,
                              void* d_out, int out_size) {
    (void)in_sizes; (void)n_in; (void)out_size;
    const float* emb = (const float*)d_in[0];
    const float* lab = (const float*)d_in[1];
    const float* wq  = (const float*)d_in[2];
    const float* bq  = (const float*)d_in[3];
    const float* wk  = (const float*)d_in[4];
    const float* bk  = (const float*)d_in[5];
    const float* wv  = (const float*)d_in[6];
    const float* bv  = (const float*)d_in[7];
    const float* w1  = (const float*)d_in[8];
    const float* w2  = (const float*)d_in[9];
    float* out = (float*)d_out;

    cudaFuncSetAttribute(convtc, cudaFuncAttributeMaxDynamicSharedMemorySize, SMEMB);
    cudaFuncSetAttribute(gtc5,  cudaFuncAttributeMaxDynamicSharedMemorySize, SMEMB);
    cudaFuncSetAttribute(gtc68, cudaFuncAttributeMaxDynamicSharedMemorySize, SMEMB);
    cudaFuncSetAttribute(gtc79, cudaFuncAttributeMaxDynamicSharedMemorySize, SMEMB);
    cudaFuncSetAttribute(flash_attn, cudaFuncAttributeMaxDynamicSharedMemorySize, FSM);

    dim3 thr(256);
    prep_all<<<9728, 256>>>(emb, wq, wk, wv, lab, w1, w2);
    convtc<<<dim3(4, 8, 48), thr, SMEMB>>>(bq, bk, bv);

    flash_attn<<<dim3(8, 128), thr, FSM>>>();

    gtc5<<<dim3(8, 2, 16), thr, SMEMB>>>();
    gtc68<<<dim3(8, 8, 32), thr, SMEMB>>>();
    softmax_kernel<<<dim3(1024, 32), thr>>>();
    gtc79<<<dim3(8, 4, 32), thr, SMEMB>>>();

    l2norm_kernel<<<dim3(16384, 2), dim3(128)>>>(out);
}